// round 11
// baseline (speedup 1.0000x reference)
#include <cuda_runtime.h>
#include <cuda_fp16.h>
#include <cstdint>

#define BATCH 4
#define SEQ   1024
#define NXD   1024
#define NHEAD 16
#define HDIM  64
#define GK    1024

// Scratch (allocation-free rule: __device__ globals) — fp16 internals
__device__ __half g_q[(size_t)BATCH * NHEAD * SEQ * HDIM];   // pre-scaled by 1/8
__device__ __half g_k[(size_t)BATCH * NHEAD * SEQ * HDIM];
__device__ __half g_v[(size_t)BATCH * NHEAD * SEQ * HDIM];   // [b,h,s,d]
__device__ __half g_vT[(size_t)BATCH * NHEAD * SEQ * HDIM];  // [b,h,d,s]
__device__ __half g_a[(size_t)BATCH * SEQ * NXD];
__device__ __half g_x[(size_t)BATCH * SEQ * NXD];
__device__ __half g_wT_attn[(size_t)3 * NXD * NXD];          // [3072,1024]
__device__ __half g_wT_proj[(size_t)NXD * NXD];              // [1024,1024]

__device__ __forceinline__ uint32_t smem_u32(const void* p) {
    uint32_t a;
    asm("{ .reg .u64 t; cvta.to.shared.u64 t, %1; cvt.u32.u64 %0, t; }"
        : "=r"(a) : "l"(p));
    return a;
}
__device__ __forceinline__ uint32_t packh2(float a, float b) {
    __half2 h = __floats2half2_rn(a, b);
    return *(uint32_t*)&h;
}
__device__ __forceinline__ void cp16(uint32_t dst, const void* src) {
    asm volatile("cp.async.cg.shared.global [%0], [%1], 16;"
                 :: "r"(dst), "l"(src) : "memory");
}
__device__ __forceinline__ void cp_commit() {
    asm volatile("cp.async.commit_group;" ::: "memory");
}
__device__ __forceinline__ void mma_f16(float* d,
    uint32_t a0, uint32_t a1, uint32_t a2, uint32_t a3,
    uint32_t b0, uint32_t b1)
{
    asm volatile(
        "mma.sync.aligned.m16n8k16.row.col.f32.f16.f16.f32 "
        "{%0,%1,%2,%3}, {%4,%5,%6,%7}, {%8,%9}, {%0,%1,%2,%3};"
        : "+f"(d[0]), "+f"(d[1]), "+f"(d[2]), "+f"(d[3])
        : "r"(a0), "r"(a1), "r"(a2), "r"(a3), "r"(b0), "r"(b1));
}

// ---------------------------------------------------------------------------
__global__ void __launch_bounds__(256) cvt_copy_kernel(
    const float* __restrict__ src, __half* __restrict__ dst)
{
    int i = blockIdx.x * 256 + threadIdx.x;
    float4 v = ((const float4*)src)[i];
    uint2 o;
    o.x = packh2(v.x, v.y);
    o.y = packh2(v.z, v.w);
    ((uint2*)dst)[i] = o;
}

__global__ void __launch_bounds__(256) transpose_kernel(
    const float* __restrict__ src, __half* __restrict__ dst, int R, int C)
{
    __shared__ float tile[32][33];
    int c0 = blockIdx.x * 32, r0 = blockIdx.y * 32;
    int tx = threadIdx.x & 31, ty = threadIdx.x >> 5;
#pragma unroll
    for (int i = 0; i < 32; i += 8)
        tile[ty + i][tx] = src[(size_t)(r0 + ty + i) * C + c0 + tx];
    __syncthreads();
#pragma unroll
    for (int i = 0; i < 32; i += 8)
        dst[(size_t)(c0 + ty + i) * R + r0 + tx] = __float2half(tile[tx][ty + i]);
}

// V transpose fp16: g_v [b,h,s,d] -> g_vT [b,h,d,s]
__global__ void __launch_bounds__(256) vtrans_kernel()
{
    __shared__ __half tile[32][33];
    int bh = blockIdx.z;
    int s0 = blockIdx.x * 32, d0 = blockIdx.y * 32;
    const __half* src = g_v + (size_t)bh * SEQ * HDIM;
    __half* dst = g_vT + (size_t)bh * SEQ * HDIM;
    int tx = threadIdx.x & 31, ty = threadIdx.x >> 5;
#pragma unroll
    for (int i = 0; i < 32; i += 8)
        tile[ty + i][tx] = src[(size_t)(s0 + ty + i) * HDIM + d0 + tx];
    __syncthreads();
#pragma unroll
    for (int i = 0; i < 32; i += 8)
        dst[(size_t)(d0 + ty + i) * SEQ + s0 + tx] = tile[tx][ty + i];
}

// ---------------------------------------------------------------------------
// fp16 mma.sync GEMM (fp32 accum). Block 128x128, BK=64, 8 warps (32x64 each,
// 4x2 grid), 3-stage cp.async, 2 CTAs/SM (independent barriers).
// C[m][n] = sum_k A[m][k] * BT[n][k] + bias[n]
// ---------------------------------------------------------------------------
#define TLD2 36                          // u32 per smem row (72 halves)
#define STG32 (256 * TLD2)               // u32 per stage (A 128 + B 128 rows)
#define GEMM_SMEM (3 * STG32 * 4)        // 110,592 B -> 2 CTAs/SM

__global__ void __launch_bounds__(256, 2) gemm_mma_kernel(
    const __half* __restrict__ A, const __half* __restrict__ BT,
    const float* __restrict__ bias, float* __restrict__ Cout,
    float* __restrict__ present, int mode)
{
    extern __shared__ uint32_t sm32[];

    const int t = threadIdx.x;
    const int lane = t & 31, w = t >> 5;
    const int wm = w >> 1, wn = w & 1;          // 4 x 2 warps, 32x64 each
    const int qr = lane >> 2, qc = lane & 3;
    const int m0 = blockIdx.y * 128;
    const int n0 = blockIdx.x * 128;

    uint32_t sa_[3], sb_[3];
#pragma unroll
    for (int s = 0; s < 3; s++) {
        sa_[s] = smem_u32(sm32 + s * STG32);
        sb_[s] = sa_[s] + 128 * TLD2 * 4;
    }

    float acc[2][8][4];
#pragma unroll
    for (int mt = 0; mt < 2; mt++)
#pragma unroll
        for (int nt = 0; nt < 8; nt++)
#pragma unroll
            for (int r = 0; r < 4; r++) acc[mt][nt][r] = 0.f;

    // per stage: A 1024 chunks (128 rows x 8), B 1024 chunks; 16B = 8 halves
#pragma unroll
    for (int s = 0; s < 2; s++) {
        const int k0 = s * 64;
#pragma unroll
        for (int i = 0; i < 4; i++) {
            int idx = t + i * 256;
            int row = idx >> 3, ch = idx & 7;
            cp16(sa_[s] + ((uint32_t)row * TLD2 + ch * 4) * 4,
                 A + (size_t)(m0 + row) * GK + k0 + ch * 8);
            cp16(sb_[s] + ((uint32_t)row * TLD2 + ch * 4) * 4,
                 BT + (size_t)(n0 + row) * GK + k0 + ch * 8);
        }
        cp_commit();
    }

    for (int kb = 0; kb < 16; kb++) {
        if (kb < 14)
            asm volatile("cp.async.wait_group 1;" ::: "memory");
        else
            asm volatile("cp.async.wait_group 0;" ::: "memory");
        __syncthreads();

        if (kb + 2 < 16) {
            const int s = (kb + 2) % 3;
            const int k0 = (kb + 2) * 64;
#pragma unroll
            for (int i = 0; i < 4; i++) {
                int idx = t + i * 256;
                int row = idx >> 3, ch = idx & 7;
                cp16(sa_[s] + ((uint32_t)row * TLD2 + ch * 4) * 4,
                     A + (size_t)(m0 + row) * GK + k0 + ch * 8);
                cp16(sb_[s] + ((uint32_t)row * TLD2 + ch * 4) * 4,
                     BT + (size_t)(n0 + row) * GK + k0 + ch * 8);
            }
            cp_commit();
        }

        const uint32_t* ab = sm32 + (kb % 3) * STG32;
        const uint32_t* bb = ab + 128 * TLD2;
#pragma unroll
        for (int ks = 0; ks < 4; ks++) {        // 4 k16 steps per BK=64
            const int k2 = ks * 8;              // h2 offset
            uint32_t af[2][4], bf[8][2];
#pragma unroll
            for (int mt = 0; mt < 2; mt++) {
                const uint32_t* ap = ab + (wm * 32 + mt * 16 + qr) * TLD2 + k2 + qc;
                af[mt][0] = ap[0];
                af[mt][1] = ap[8 * TLD2];
                af[mt][2] = ap[4];
                af[mt][3] = ap[8 * TLD2 + 4];
            }
#pragma unroll
            for (int nt = 0; nt < 8; nt++) {
                const uint32_t* bp = bb + (wn * 64 + nt * 8 + qr) * TLD2 + k2 + qc;
                bf[nt][0] = bp[0];
                bf[nt][1] = bp[4];
            }
#pragma unroll
            for (int mt = 0; mt < 2; mt++)
#pragma unroll
                for (int nt = 0; nt < 8; nt++)
                    mma_f16(acc[mt][nt], af[mt][0], af[mt][1], af[mt][2], af[mt][3],
                            bf[nt][0], bf[nt][1]);
        }
    }

#pragma unroll
    for (int mt = 0; mt < 2; mt++) {
#pragma unroll
        for (int nt = 0; nt < 8; nt++) {
            int row = m0 + wm * 32 + mt * 16 + qr;
            int col = n0 + wn * 64 + nt * 8 + qc * 2;
            float bv0 = bias[col], bv1 = bias[col + 1];
            float v00 = acc[mt][nt][0] + bv0, v01 = acc[mt][nt][1] + bv1;
            float v10 = acc[mt][nt][2] + bv0, v11 = acc[mt][nt][3] + bv1;
            if (mode == 1) {
                *(float2*)(Cout + (size_t)row * NXD + col) = make_float2(v00, v01);
                *(float2*)(Cout + (size_t)(row + 8) * NXD + col) = make_float2(v10, v11);
            } else {
                int sec = col >> 10;
                int hn = col & 1023;
                int h = hn >> 6, d = hn & 63;
                int b0_ = row >> 10, s0_ = row & 1023;
                size_t i0 = (((size_t)b0_ * NHEAD + h) * SEQ + s0_) * HDIM + d;
                int b1_ = (row + 8) >> 10, s1_ = (row + 8) & 1023;
                size_t i1 = (((size_t)b1_ * NHEAD + h) * SEQ + s1_) * HDIM + d;
                if (sec == 0) {          // q -> scratch (scaled)
                    *(uint32_t*)(g_q + i0) = packh2(v00 * 0.125f, v01 * 0.125f);
                    *(uint32_t*)(g_q + i1) = packh2(v10 * 0.125f, v11 * 0.125f);
                } else if (sec == 1) {   // k -> present exact + half scratch
                    *(float2*)(present + i0) = make_float2(v00, v01);
                    *(float2*)(present + i1) = make_float2(v10, v11);
                    *(uint32_t*)(g_k + i0) = packh2(v00, v01);
                    *(uint32_t*)(g_k + i1) = packh2(v10, v11);
                } else {                 // v
                    float* pv = present + (size_t)BATCH * NHEAD * SEQ * HDIM;
                    *(float2*)(pv + i0) = make_float2(v00, v01);
                    *(float2*)(pv + i1) = make_float2(v10, v11);
                    *(uint32_t*)(g_v + i0) = packh2(v00, v01);
                    *(uint32_t*)(g_v + i1) = packh2(v10, v11);
                }
            }
        }
    }
}

// ---------------------------------------------------------------------------
// Attention: fp16 mma.sync (fp32 softmax/acc), P register-resident (unchanged R9)
// ---------------------------------------------------------------------------
#define ATTN_SMEM ((128 * TLD2 + 2 * 64 * TLD2 + 2 * 64 * TLD2) * 4)  // 55,296 B

__global__ void __launch_bounds__(256, 2) attn_mma_kernel()
{
    extern __shared__ uint32_t sma32[];
    uint32_t* Qs = sma32;                        // [128][36] (q, d) h2
    uint32_t* Ksb = Qs + 128 * TLD2;             // 2 x [64][36] (kpos, d) h2
    uint32_t* Vtb = Ksb + 2 * 64 * TLD2;         // 2 x [64][36] (d, kpos) h2

    const int t = threadIdx.x;
    const int lane = t & 31, w = t >> 5;
    const int qr = lane >> 2, qc = lane & 3;
    const int q0 = blockIdx.x * 128;
    const int h = blockIdx.y;
    const int b = blockIdx.z;

    const __half* qptr = g_q + ((size_t)b * NHEAD + h) * SEQ * HDIM;
    const __half* kptr = g_k + ((size_t)b * NHEAD + h) * SEQ * HDIM;
    const __half* vtp  = g_vT + ((size_t)b * NHEAD + h) * SEQ * HDIM;

    const uint32_t qs_a = smem_u32(Qs);
    const uint32_t ks_a[2] = { smem_u32(Ksb), smem_u32(Ksb + 64 * TLD2) };
    const uint32_t vs_a[2] = { smem_u32(Vtb), smem_u32(Vtb + 64 * TLD2) };

#pragma unroll
    for (int i = 0; i < 4; i++) {
        int c = t + i * 256;
        int row = c >> 3, ch = c & 7;
        cp16(qs_a + ((uint32_t)row * TLD2 + ch * 4) * 4,
             qptr + (size_t)(q0 + row) * HDIM + ch * 8);
    }
#pragma unroll
    for (int i = 0; i < 2; i++) {
        int c = t + i * 256;
        int row = c >> 3, ch = c & 7;
        uint32_t off = ((uint32_t)row * TLD2 + ch * 4) * 4;
        cp16(ks_a[0] + off, kptr + (size_t)row * HDIM + ch * 8);
        cp16(vs_a[0] + off, vtp + (size_t)row * SEQ + ch * 8);
    }
    cp_commit();

    float oacc[8][4];
#pragma unroll
    for (int nt = 0; nt < 8; nt++)
#pragma unroll
        for (int r = 0; r < 4; r++) oacc[nt][r] = 0.f;
    float m0 = -1e30f, m1 = -1e30f, l0 = 0.f, l1 = 0.f;

    const int wrow = w * 16;
    const int qg0 = q0 + wrow + qr;
    const int qg1 = qg0 + 8;
    const int qmax = q0 + wrow + 15;
    const int nj = blockIdx.x * 2 + 2;

    asm volatile("cp.async.wait_group 0;" ::: "memory");
    __syncthreads();
    uint32_t qf[4][4];
#pragma unroll
    for (int ks = 0; ks < 4; ks++) {
        const uint32_t* qp = Qs + (wrow + qr) * TLD2 + ks * 8 + qc;
        qf[ks][0] = qp[0];
        qf[ks][1] = qp[8 * TLD2];
        qf[ks][2] = qp[4];
        qf[ks][3] = qp[8 * TLD2 + 4];
    }

    for (int jt = 0; jt < nj; jt++) {
        const int j0 = jt * 64;
        if (jt > 0) {
            asm volatile("cp.async.wait_group 0;" ::: "memory");
            __syncthreads();
        }
        if (jt + 1 < nj) {
            const int buf = (jt + 1) & 1;
            const int jr = (jt + 1) * 64;
#pragma unroll
            for (int i = 0; i < 2; i++) {
                int c = t + i * 256;
                int row = c >> 3, ch = c & 7;
                uint32_t off = ((uint32_t)row * TLD2 + ch * 4) * 4;
                cp16(ks_a[buf] + off, kptr + (size_t)(jr + row) * HDIM + ch * 8);
                cp16(vs_a[buf] + off, vtp + (size_t)row * SEQ + jr + ch * 8);
            }
            cp_commit();
        }
        if (j0 > qmax) continue;

        const uint32_t* Ku = Ksb + (jt & 1) * 64 * TLD2;
        const uint32_t* Vu = Vtb + (jt & 1) * 64 * TLD2;

        float sacc[8][4];
#pragma unroll
        for (int nt = 0; nt < 8; nt++)
#pragma unroll
            for (int r = 0; r < 4; r++) sacc[nt][r] = 0.f;

#pragma unroll
        for (int ks = 0; ks < 4; ks++) {
            const int k2 = ks * 8;
#pragma unroll
            for (int nt = 0; nt < 8; nt++) {
                const uint32_t* kp = Ku + (nt * 8 + qr) * TLD2 + k2 + qc;
                mma_f16(sacc[nt], qf[ks][0], qf[ks][1], qf[ks][2], qf[ks][3],
                        kp[0], kp[4]);
            }
        }

        float rx0 = -1e30f, rx1 = -1e30f;
#pragma unroll
        for (int nt = 0; nt < 8; nt++) {
            int kg = j0 + nt * 8 + qc * 2;
            if (kg > qg0)     sacc[nt][0] = -1e30f;
            if (kg + 1 > qg0) sacc[nt][1] = -1e30f;
            if (kg > qg1)     sacc[nt][2] = -1e30f;
            if (kg + 1 > qg1) sacc[nt][3] = -1e30f;
            rx0 = fmaxf(rx0, fmaxf(sacc[nt][0], sacc[nt][1]));
            rx1 = fmaxf(rx1, fmaxf(sacc[nt][2], sacc[nt][3]));
        }
        rx0 = fmaxf(rx0, __shfl_xor_sync(0xffffffffu, rx0, 1));
        rx0 = fmaxf(rx0, __shfl_xor_sync(0xffffffffu, rx0, 2));
        rx1 = fmaxf(rx1, __shfl_xor_sync(0xffffffffu, rx1, 1));
        rx1 = fmaxf(rx1, __shfl_xor_sync(0xffffffffu, rx1, 2));

        float nm0 = fmaxf(m0, rx0), nm1 = fmaxf(m1, rx1);
        float cr0 = __expf(m0 - nm0), cr1 = __expf(m1 - nm1);

        float rs0 = 0.f, rs1 = 0.f;
        uint32_t plo[8], phi[8];
#pragma unroll
        for (int nt = 0; nt < 8; nt++) {
            float p00 = __expf(sacc[nt][0] - nm0);
            float p01 = __expf(sacc[nt][1] - nm0);
            float p10 = __expf(sacc[nt][2] - nm1);
            float p11 = __expf(sacc[nt][3] - nm1);
            rs0 += p00 + p01;
            rs1 += p10 + p11;
            plo[nt] = packh2(p00, p01);
            phi[nt] = packh2(p10, p11);
        }
        rs0 += __shfl_xor_sync(0xffffffffu, rs0, 1);
        rs0 += __shfl_xor_sync(0xffffffffu, rs0, 2);
        rs1 += __shfl_xor_sync(0xffffffffu, rs1, 1);
        rs1 += __shfl_xor_sync(0xffffffffu, rs1, 2);

        l0 = l0 * cr0 + rs0;  m0 = nm0;
        l1 = l1 * cr1 + rs1;  m1 = nm1;
#pragma unroll
        for (int nt = 0; nt < 8; nt++) {
            oacc[nt][0] *= cr0;  oacc[nt][1] *= cr0;
            oacc[nt][2] *= cr1;  oacc[nt][3] *= cr1;
        }

#pragma unroll
        for (int j = 0; j < 4; j++) {
            uint32_t a0 = plo[2 * j], a1 = phi[2 * j];
            uint32_t a2 = plo[2 * j + 1], a3 = phi[2 * j + 1];
            const int k2 = j * 8;
#pragma unroll
            for (int nt = 0; nt < 8; nt++) {
                const uint32_t* vp = Vu + (nt * 8 + qr) * TLD2 + k2 + qc;
                mma_f16(oacc[nt], a0, a1, a2, a3, vp[0], vp[4]);
            }
        }
    }

    __syncthreads();
    float inv0 = 1.f / l0, inv1 = 1.f / l1;
#pragma unroll
    for (int nt = 0; nt < 8; nt++) {
        Qs[(wrow + qr) * TLD2 + nt * 4 + qc] =
            packh2(oacc[nt][0] * inv0, oacc[nt][1] * inv0);
        Qs[(wrow + qr + 8) * TLD2 + nt * 4 + qc] =
            packh2(oacc[nt][2] * inv1, oacc[nt][3] * inv1);
    }
    __syncthreads();
    for (int idx = t; idx < 128 * 32; idx += 256) {
        int row = idx >> 5, c2 = idx & 31;
        *(uint32_t*)(g_a + ((size_t)b * SEQ + q0 + row) * NXD + h * HDIM + c2 * 2) =
            Qs[row * TLD2 + c2];
    }
}

// ---------------------------------------------------------------------------
extern "C" void kernel_launch(void* const* d_in, const int* in_sizes, int n_in,
                              void* d_out, int out_size)
{
    const float* x      = (const float*)d_in[0];
    const float* w_attn = (const float*)d_in[1];
    const float* b_attn = (const float*)d_in[2];
    const float* w_proj = (const float*)d_in[3];
    const float* b_proj = (const float*)d_in[4];

    float* out = (float*)d_out;
    float* present = out + (size_t)BATCH * SEQ * NXD;  // (2,B,NH,S,HD)

    cudaFuncSetAttribute(gemm_mma_kernel,
                         cudaFuncAttributeMaxDynamicSharedMemorySize, GEMM_SMEM);
    cudaFuncSetAttribute(attn_mma_kernel,
                         cudaFuncAttributeMaxDynamicSharedMemorySize, ATTN_SMEM);

    __half* wT_attn;  cudaGetSymbolAddress((void**)&wT_attn, g_wT_attn);
    __half* wT_proj;  cudaGetSymbolAddress((void**)&wT_proj, g_wT_proj);
    __half* a_ptr;    cudaGetSymbolAddress((void**)&a_ptr, g_a);
    __half* x_ptr;    cudaGetSymbolAddress((void**)&x_ptr, g_x);

    cvt_copy_kernel<<<(BATCH * SEQ * NXD / 4) / 256, 256>>>(x, x_ptr);
    transpose_kernel<<<dim3(3 * NXD / 32, NXD / 32), 256>>>(w_attn, wT_attn, NXD, 3 * NXD);
    transpose_kernel<<<dim3(NXD / 32, NXD / 32), 256>>>(w_proj, wT_proj, NXD, NXD);

    gemm_mma_kernel<<<dim3(3 * NXD / 128, BATCH * SEQ / 128), 256, GEMM_SMEM>>>(
        x_ptr, wT_attn, b_attn, nullptr, present, 0);

    vtrans_kernel<<<dim3(SEQ / 32, HDIM / 32, BATCH * NHEAD), 256>>>();

    attn_mma_kernel<<<dim3(SEQ / 128, NHEAD, BATCH), 256, ATTN_SMEM>>>();

    gemm_mma_kernel<<<dim3(NXD / 128, BATCH * SEQ / 128), 256, GEMM_SMEM>>>(
        a_ptr, wT_proj, b_proj, out, nullptr, 1);
}

// round 12
// speedup vs baseline: 1.0183x; 1.0183x over previous
#include <cuda_runtime.h>
#include <cuda_fp16.h>
#include <cstdint>

#define BATCH 4
#define SEQ   1024
#define NXD   1024
#define NHEAD 16
#define HDIM  64
#define GK    1024

// Scratch (allocation-free rule: __device__ globals) — fp16 internals
__device__ __half g_q[(size_t)BATCH * NHEAD * SEQ * HDIM];   // pre-scaled by 1/8
__device__ __half g_k[(size_t)BATCH * NHEAD * SEQ * HDIM];
__device__ __half g_v[(size_t)BATCH * NHEAD * SEQ * HDIM];   // [b,h,s,d]
__device__ __half g_vT[(size_t)BATCH * NHEAD * SEQ * HDIM];  // [b,h,d,s]
__device__ __half g_a[(size_t)BATCH * SEQ * NXD];
__device__ __half g_x[(size_t)BATCH * SEQ * NXD];
__device__ __half g_wT_attn[(size_t)3 * NXD * NXD];          // [3072,1024]
__device__ __half g_wT_proj[(size_t)NXD * NXD];              // [1024,1024]

__device__ __forceinline__ uint32_t smem_u32(const void* p) {
    uint32_t a;
    asm("{ .reg .u64 t; cvta.to.shared.u64 t, %1; cvt.u32.u64 %0, t; }"
        : "=r"(a) : "l"(p));
    return a;
}
__device__ __forceinline__ uint32_t packh2(float a, float b) {
    __half2 h = __floats2half2_rn(a, b);
    return *(uint32_t*)&h;
}
__device__ __forceinline__ void cp16(uint32_t dst, const void* src) {
    asm volatile("cp.async.cg.shared.global [%0], [%1], 16;"
                 :: "r"(dst), "l"(src) : "memory");
}
__device__ __forceinline__ void cp_commit() {
    asm volatile("cp.async.commit_group;" ::: "memory");
}
__device__ __forceinline__ void mma_f16(float* d,
    uint32_t a0, uint32_t a1, uint32_t a2, uint32_t a3,
    uint32_t b0, uint32_t b1)
{
    asm volatile(
        "mma.sync.aligned.m16n8k16.row.col.f32.f16.f16.f32 "
        "{%0,%1,%2,%3}, {%4,%5,%6,%7}, {%8,%9}, {%0,%1,%2,%3};"
        : "+f"(d[0]), "+f"(d[1]), "+f"(d[2]), "+f"(d[3])
        : "r"(a0), "r"(a1), "r"(a2), "r"(a3), "r"(b0), "r"(b1));
}

// ---------------------------------------------------------------------------
// Fused prep: one launch does x->fp16 copy + both weight transposes.
// blocks [0,4096): cvt_copy; [4096,7168): w_attn T; [7168,8192): w_proj T.
// ---------------------------------------------------------------------------
__global__ void __launch_bounds__(256) prep_kernel(
    const float* __restrict__ x,
    const float* __restrict__ w_attn,
    const float* __restrict__ w_proj)
{
    const int bid = blockIdx.x;
    if (bid < 4096) {
        int i = bid * 256 + threadIdx.x;
        float4 v = ((const float4*)x)[i];
        uint2 o;
        o.x = packh2(v.x, v.y);
        o.y = packh2(v.z, v.w);
        ((uint2*)g_x)[i] = o;
        return;
    }
    __shared__ float tile[32][33];
    const float* src;  __half* dst;  int R, C, c0, r0;
    if (bid < 7168) {
        int b2 = bid - 4096;             // w_attn: 96 x 32 tile grid
        src = w_attn;  dst = g_wT_attn;  R = NXD;  C = 3 * NXD;
        c0 = (b2 % 96) * 32;  r0 = (b2 / 96) * 32;
    } else {
        int b2 = bid - 7168;             // w_proj: 32 x 32
        src = w_proj;  dst = g_wT_proj;  R = NXD;  C = NXD;
        c0 = (b2 % 32) * 32;  r0 = (b2 / 32) * 32;
    }
    int tx = threadIdx.x & 31, ty = threadIdx.x >> 5;
#pragma unroll
    for (int i = 0; i < 32; i += 8)
        tile[ty + i][tx] = src[(size_t)(r0 + ty + i) * C + c0 + tx];
    __syncthreads();
#pragma unroll
    for (int i = 0; i < 32; i += 8)
        dst[(size_t)(c0 + ty + i) * R + r0 + tx] = __float2half(tile[tx][ty + i]);
}

// V transpose fp16: g_v [b,h,s,d] -> g_vT [b,h,d,s]
__global__ void __launch_bounds__(256) vtrans_kernel()
{
    __shared__ __half tile[32][33];
    int bh = blockIdx.z;
    int s0 = blockIdx.x * 32, d0 = blockIdx.y * 32;
    const __half* src = g_v + (size_t)bh * SEQ * HDIM;
    __half* dst = g_vT + (size_t)bh * SEQ * HDIM;
    int tx = threadIdx.x & 31, ty = threadIdx.x >> 5;
#pragma unroll
    for (int i = 0; i < 32; i += 8)
        tile[ty + i][tx] = src[(size_t)(s0 + ty + i) * HDIM + d0 + tx];
    __syncthreads();
#pragma unroll
    for (int i = 0; i < 32; i += 8)
        dst[(size_t)(d0 + ty + i) * SEQ + s0 + tx] = tile[tx][ty + i];
}

// ---------------------------------------------------------------------------
// fp16 mma.sync GEMM (fp32 accum) — R11 config (verified best).
// Block 128x128, BK=64, 8 warps (32x64), 3-stage cp.async, 2 CTAs/SM.
// ---------------------------------------------------------------------------
#define TLD2 36                          // u32 per smem row (72 halves)
#define STG32 (256 * TLD2)               // u32 per stage
#define GEMM_SMEM (3 * STG32 * 4)        // 110,592 B

__global__ void __launch_bounds__(256, 2) gemm_mma_kernel(
    const __half* __restrict__ A, const __half* __restrict__ BT,
    const float* __restrict__ bias, float* __restrict__ Cout,
    float* __restrict__ present, int mode)
{
    extern __shared__ uint32_t sm32[];

    const int t = threadIdx.x;
    const int lane = t & 31, w = t >> 5;
    const int wm = w >> 1, wn = w & 1;          // 4 x 2 warps, 32x64 each
    const int qr = lane >> 2, qc = lane & 3;
    const int m0 = blockIdx.y * 128;
    const int n0 = blockIdx.x * 128;

    uint32_t sa_[3], sb_[3];
#pragma unroll
    for (int s = 0; s < 3; s++) {
        sa_[s] = smem_u32(sm32 + s * STG32);
        sb_[s] = sa_[s] + 128 * TLD2 * 4;
    }

    float acc[2][8][4];
#pragma unroll
    for (int mt = 0; mt < 2; mt++)
#pragma unroll
        for (int nt = 0; nt < 8; nt++)
#pragma unroll
            for (int r = 0; r < 4; r++) acc[mt][nt][r] = 0.f;

#pragma unroll
    for (int s = 0; s < 2; s++) {
        const int k0 = s * 64;
#pragma unroll
        for (int i = 0; i < 4; i++) {
            int idx = t + i * 256;
            int row = idx >> 3, ch = idx & 7;
            cp16(sa_[s] + ((uint32_t)row * TLD2 + ch * 4) * 4,
                 A + (size_t)(m0 + row) * GK + k0 + ch * 8);
            cp16(sb_[s] + ((uint32_t)row * TLD2 + ch * 4) * 4,
                 BT + (size_t)(n0 + row) * GK + k0 + ch * 8);
        }
        cp_commit();
    }

    for (int kb = 0; kb < 16; kb++) {
        if (kb < 14)
            asm volatile("cp.async.wait_group 1;" ::: "memory");
        else
            asm volatile("cp.async.wait_group 0;" ::: "memory");
        __syncthreads();

        if (kb + 2 < 16) {
            const int s = (kb + 2) % 3;
            const int k0 = (kb + 2) * 64;
#pragma unroll
            for (int i = 0; i < 4; i++) {
                int idx = t + i * 256;
                int row = idx >> 3, ch = idx & 7;
                cp16(sa_[s] + ((uint32_t)row * TLD2 + ch * 4) * 4,
                     A + (size_t)(m0 + row) * GK + k0 + ch * 8);
                cp16(sb_[s] + ((uint32_t)row * TLD2 + ch * 4) * 4,
                     BT + (size_t)(n0 + row) * GK + k0 + ch * 8);
            }
            cp_commit();
        }

        const uint32_t* ab = sm32 + (kb % 3) * STG32;
        const uint32_t* bb = ab + 128 * TLD2;
#pragma unroll
        for (int ks = 0; ks < 4; ks++) {
            const int k2 = ks * 8;
            uint32_t af[2][4], bf[8][2];
#pragma unroll
            for (int mt = 0; mt < 2; mt++) {
                const uint32_t* ap = ab + (wm * 32 + mt * 16 + qr) * TLD2 + k2 + qc;
                af[mt][0] = ap[0];
                af[mt][1] = ap[8 * TLD2];
                af[mt][2] = ap[4];
                af[mt][3] = ap[8 * TLD2 + 4];
            }
#pragma unroll
            for (int nt = 0; nt < 8; nt++) {
                const uint32_t* bp = bb + (wn * 64 + nt * 8 + qr) * TLD2 + k2 + qc;
                bf[nt][0] = bp[0];
                bf[nt][1] = bp[4];
            }
#pragma unroll
            for (int mt = 0; mt < 2; mt++)
#pragma unroll
                for (int nt = 0; nt < 8; nt++)
                    mma_f16(acc[mt][nt], af[mt][0], af[mt][1], af[mt][2], af[mt][3],
                            bf[nt][0], bf[nt][1]);
        }
    }

#pragma unroll
    for (int mt = 0; mt < 2; mt++) {
#pragma unroll
        for (int nt = 0; nt < 8; nt++) {
            int row = m0 + wm * 32 + mt * 16 + qr;
            int col = n0 + wn * 64 + nt * 8 + qc * 2;
            float bv0 = bias[col], bv1 = bias[col + 1];
            float v00 = acc[mt][nt][0] + bv0, v01 = acc[mt][nt][1] + bv1;
            float v10 = acc[mt][nt][2] + bv0, v11 = acc[mt][nt][3] + bv1;
            if (mode == 1) {
                *(float2*)(Cout + (size_t)row * NXD + col) = make_float2(v00, v01);
                *(float2*)(Cout + (size_t)(row + 8) * NXD + col) = make_float2(v10, v11);
            } else {
                int sec = col >> 10;
                int hn = col & 1023;
                int h = hn >> 6, d = hn & 63;
                int b0_ = row >> 10, s0_ = row & 1023;
                size_t i0 = (((size_t)b0_ * NHEAD + h) * SEQ + s0_) * HDIM + d;
                int b1_ = (row + 8) >> 10, s1_ = (row + 8) & 1023;
                size_t i1 = (((size_t)b1_ * NHEAD + h) * SEQ + s1_) * HDIM + d;
                if (sec == 0) {          // q -> scratch (scaled)
                    *(uint32_t*)(g_q + i0) = packh2(v00 * 0.125f, v01 * 0.125f);
                    *(uint32_t*)(g_q + i1) = packh2(v10 * 0.125f, v11 * 0.125f);
                } else if (sec == 1) {   // k -> present exact + half scratch
                    *(float2*)(present + i0) = make_float2(v00, v01);
                    *(float2*)(present + i1) = make_float2(v10, v11);
                    *(uint32_t*)(g_k + i0) = packh2(v00, v01);
                    *(uint32_t*)(g_k + i1) = packh2(v10, v11);
                } else {                 // v
                    float* pv = present + (size_t)BATCH * NHEAD * SEQ * HDIM;
                    *(float2*)(pv + i0) = make_float2(v00, v01);
                    *(float2*)(pv + i1) = make_float2(v10, v11);
                    *(uint32_t*)(g_v + i0) = packh2(v00, v01);
                    *(uint32_t*)(g_v + i1) = packh2(v10, v11);
                }
            }
        }
    }
}

// ---------------------------------------------------------------------------
// Attention: fp16 mma.sync, P register-resident. REVERSED q-tile order:
// longest (most j-tiles) CTAs get the lowest blockIdx.x -> start first.
// ---------------------------------------------------------------------------
#define ATTN_SMEM ((128 * TLD2 + 2 * 64 * TLD2 + 2 * 64 * TLD2) * 4)  // 55,296 B

__global__ void __launch_bounds__(256, 2) attn_mma_kernel()
{
    extern __shared__ uint32_t sma32[];
    uint32_t* Qs = sma32;                        // [128][36] (q, d) h2
    uint32_t* Ksb = Qs + 128 * TLD2;             // 2 x [64][36] (kpos, d) h2
    uint32_t* Vtb = Ksb + 2 * 64 * TLD2;         // 2 x [64][36] (d, kpos) h2

    const int t = threadIdx.x;
    const int lane = t & 31, w = t >> 5;
    const int qr = lane >> 2, qc = lane & 3;
    const int xr = (int)gridDim.x - 1 - (int)blockIdx.x;   // reversed tile id
    const int q0 = xr * 128;
    const int h = blockIdx.y;
    const int b = blockIdx.z;

    const __half* qptr = g_q + ((size_t)b * NHEAD + h) * SEQ * HDIM;
    const __half* kptr = g_k + ((size_t)b * NHEAD + h) * SEQ * HDIM;
    const __half* vtp  = g_vT + ((size_t)b * NHEAD + h) * SEQ * HDIM;

    const uint32_t qs_a = smem_u32(Qs);
    const uint32_t ks_a[2] = { smem_u32(Ksb), smem_u32(Ksb + 64 * TLD2) };
    const uint32_t vs_a[2] = { smem_u32(Vtb), smem_u32(Vtb + 64 * TLD2) };

#pragma unroll
    for (int i = 0; i < 4; i++) {
        int c = t + i * 256;
        int row = c >> 3, ch = c & 7;
        cp16(qs_a + ((uint32_t)row * TLD2 + ch * 4) * 4,
             qptr + (size_t)(q0 + row) * HDIM + ch * 8);
    }
#pragma unroll
    for (int i = 0; i < 2; i++) {
        int c = t + i * 256;
        int row = c >> 3, ch = c & 7;
        uint32_t off = ((uint32_t)row * TLD2 + ch * 4) * 4;
        cp16(ks_a[0] + off, kptr + (size_t)row * HDIM + ch * 8);
        cp16(vs_a[0] + off, vtp + (size_t)row * SEQ + ch * 8);
    }
    cp_commit();

    float oacc[8][4];
#pragma unroll
    for (int nt = 0; nt < 8; nt++)
#pragma unroll
        for (int r = 0; r < 4; r++) oacc[nt][r] = 0.f;
    float m0 = -1e30f, m1 = -1e30f, l0 = 0.f, l1 = 0.f;

    const int wrow = w * 16;
    const int qg0 = q0 + wrow + qr;
    const int qg1 = qg0 + 8;
    const int qmax = q0 + wrow + 15;
    const int nj = xr * 2 + 2;

    asm volatile("cp.async.wait_group 0;" ::: "memory");
    __syncthreads();
    uint32_t qf[4][4];
#pragma unroll
    for (int ks = 0; ks < 4; ks++) {
        const uint32_t* qp = Qs + (wrow + qr) * TLD2 + ks * 8 + qc;
        qf[ks][0] = qp[0];
        qf[ks][1] = qp[8 * TLD2];
        qf[ks][2] = qp[4];
        qf[ks][3] = qp[8 * TLD2 + 4];
    }

    for (int jt = 0; jt < nj; jt++) {
        const int j0 = jt * 64;
        if (jt > 0) {
            asm volatile("cp.async.wait_group 0;" ::: "memory");
            __syncthreads();
        }
        if (jt + 1 < nj) {
            const int buf = (jt + 1) & 1;
            const int jr = (jt + 1) * 64;
#pragma unroll
            for (int i = 0; i < 2; i++) {
                int c = t + i * 256;
                int row = c >> 3, ch = c & 7;
                uint32_t off = ((uint32_t)row * TLD2 + ch * 4) * 4;
                cp16(ks_a[buf] + off, kptr + (size_t)(jr + row) * HDIM + ch * 8);
                cp16(vs_a[buf] + off, vtp + (size_t)row * SEQ + jr + ch * 8);
            }
            cp_commit();
        }
        if (j0 > qmax) continue;

        const uint32_t* Ku = Ksb + (jt & 1) * 64 * TLD2;
        const uint32_t* Vu = Vtb + (jt & 1) * 64 * TLD2;

        float sacc[8][4];
#pragma unroll
        for (int nt = 0; nt < 8; nt++)
#pragma unroll
            for (int r = 0; r < 4; r++) sacc[nt][r] = 0.f;

#pragma unroll
        for (int ks = 0; ks < 4; ks++) {
            const int k2 = ks * 8;
#pragma unroll
            for (int nt = 0; nt < 8; nt++) {
                const uint32_t* kp = Ku + (nt * 8 + qr) * TLD2 + k2 + qc;
                mma_f16(sacc[nt], qf[ks][0], qf[ks][1], qf[ks][2], qf[ks][3],
                        kp[0], kp[4]);
            }
        }

        float rx0 = -1e30f, rx1 = -1e30f;
#pragma unroll
        for (int nt = 0; nt < 8; nt++) {
            int kg = j0 + nt * 8 + qc * 2;
            if (kg > qg0)     sacc[nt][0] = -1e30f;
            if (kg + 1 > qg0) sacc[nt][1] = -1e30f;
            if (kg > qg1)     sacc[nt][2] = -1e30f;
            if (kg + 1 > qg1) sacc[nt][3] = -1e30f;
            rx0 = fmaxf(rx0, fmaxf(sacc[nt][0], sacc[nt][1]));
            rx1 = fmaxf(rx1, fmaxf(sacc[nt][2], sacc[nt][3]));
        }
        rx0 = fmaxf(rx0, __shfl_xor_sync(0xffffffffu, rx0, 1));
        rx0 = fmaxf(rx0, __shfl_xor_sync(0xffffffffu, rx0, 2));
        rx1 = fmaxf(rx1, __shfl_xor_sync(0xffffffffu, rx1, 1));
        rx1 = fmaxf(rx1, __shfl_xor_sync(0xffffffffu, rx1, 2));

        float nm0 = fmaxf(m0, rx0), nm1 = fmaxf(m1, rx1);
        float cr0 = __expf(m0 - nm0), cr1 = __expf(m1 - nm1);

        float rs0 = 0.f, rs1 = 0.f;
        uint32_t plo[8], phi[8];
#pragma unroll
        for (int nt = 0; nt < 8; nt++) {
            float p00 = __expf(sacc[nt][0] - nm0);
            float p01 = __expf(sacc[nt][1] - nm0);
            float p10 = __expf(sacc[nt][2] - nm1);
            float p11 = __expf(sacc[nt][3] - nm1);
            rs0 += p00 + p01;
            rs1 += p10 + p11;
            plo[nt] = packh2(p00, p01);
            phi[nt] = packh2(p10, p11);
        }
        rs0 += __shfl_xor_sync(0xffffffffu, rs0, 1);
        rs0 += __shfl_xor_sync(0xffffffffu, rs0, 2);
        rs1 += __shfl_xor_sync(0xffffffffu, rs1, 1);
        rs1 += __shfl_xor_sync(0xffffffffu, rs1, 2);

        l0 = l0 * cr0 + rs0;  m0 = nm0;
        l1 = l1 * cr1 + rs1;  m1 = nm1;
#pragma unroll
        for (int nt = 0; nt < 8; nt++) {
            oacc[nt][0] *= cr0;  oacc[nt][1] *= cr0;
            oacc[nt][2] *= cr1;  oacc[nt][3] *= cr1;
        }

#pragma unroll
        for (int j = 0; j < 4; j++) {
            uint32_t a0 = plo[2 * j], a1 = phi[2 * j];
            uint32_t a2 = plo[2 * j + 1], a3 = phi[2 * j + 1];
            const int k2 = j * 8;
#pragma unroll
            for (int nt = 0; nt < 8; nt++) {
                const uint32_t* vp = Vu + (nt * 8 + qr) * TLD2 + k2 + qc;
                mma_f16(oacc[nt], a0, a1, a2, a3, vp[0], vp[4]);
            }
        }
    }

    __syncthreads();
    float inv0 = 1.f / l0, inv1 = 1.f / l1;
#pragma unroll
    for (int nt = 0; nt < 8; nt++) {
        Qs[(wrow + qr) * TLD2 + nt * 4 + qc] =
            packh2(oacc[nt][0] * inv0, oacc[nt][1] * inv0);
        Qs[(wrow + qr + 8) * TLD2 + nt * 4 + qc] =
            packh2(oacc[nt][2] * inv1, oacc[nt][3] * inv1);
    }
    __syncthreads();
    for (int idx = t; idx < 128 * 32; idx += 256) {
        int row = idx >> 5, c2 = idx & 31;
        *(uint32_t*)(g_a + ((size_t)b * SEQ + q0 + row) * NXD + h * HDIM + c2 * 2) =
            Qs[row * TLD2 + c2];
    }
}

// ---------------------------------------------------------------------------
extern "C" void kernel_launch(void* const* d_in, const int* in_sizes, int n_in,
                              void* d_out, int out_size)
{
    const float* x      = (const float*)d_in[0];
    const float* w_attn = (const float*)d_in[1];
    const float* b_attn = (const float*)d_in[2];
    const float* w_proj = (const float*)d_in[3];
    const float* b_proj = (const float*)d_in[4];

    float* out = (float*)d_out;
    float* present = out + (size_t)BATCH * SEQ * NXD;  // (2,B,NH,S,HD)

    cudaFuncSetAttribute(gemm_mma_kernel,
                         cudaFuncAttributeMaxDynamicSharedMemorySize, GEMM_SMEM);
    cudaFuncSetAttribute(attn_mma_kernel,
                         cudaFuncAttributeMaxDynamicSharedMemorySize, ATTN_SMEM);

    __half* wT_attn;  cudaGetSymbolAddress((void**)&wT_attn, g_wT_attn);
    __half* wT_proj;  cudaGetSymbolAddress((void**)&wT_proj, g_wT_proj);
    __half* a_ptr;    cudaGetSymbolAddress((void**)&a_ptr, g_a);
    __half* x_ptr;    cudaGetSymbolAddress((void**)&x_ptr, g_x);

    prep_kernel<<<8192, 256>>>(x, w_attn, w_proj);

    gemm_mma_kernel<<<dim3(3 * NXD / 128, BATCH * SEQ / 128), 256, GEMM_SMEM>>>(
        x_ptr, wT_attn, b_attn, nullptr, present, 0);

    vtrans_kernel<<<dim3(SEQ / 32, HDIM / 32, BATCH * NHEAD), 256>>>();

    attn_mma_kernel<<<dim3(SEQ / 128, NHEAD, BATCH), 256, ATTN_SMEM>>>();

    gemm_mma_kernel<<<dim3(NXD / 128, BATCH * SEQ / 128), 256, GEMM_SMEM>>>(
        a_ptr, wT_proj, b_proj, out, nullptr, 1);
}

// round 13
// speedup vs baseline: 1.0603x; 1.0412x over previous
#include <cuda_runtime.h>
#include <cuda_fp16.h>
#include <cstdint>

#define BATCH 4
#define SEQ   1024
#define NXD   1024
#define NHEAD 16
#define HDIM  64
#define GK    1024

// Scratch (allocation-free rule: __device__ globals) — fp16 internals
__device__ __half g_q[(size_t)BATCH * NHEAD * SEQ * HDIM];   // pre-scaled by 1/8
__device__ __half g_k[(size_t)BATCH * NHEAD * SEQ * HDIM];
__device__ __half g_v[(size_t)BATCH * NHEAD * SEQ * HDIM];   // [b,h,s,d]
__device__ __half g_vT[(size_t)BATCH * NHEAD * SEQ * HDIM];  // [b,h,d,s]
__device__ __half g_a[(size_t)BATCH * SEQ * NXD];
__device__ __half g_x[(size_t)BATCH * SEQ * NXD];
__device__ __half g_wT_attn[(size_t)3 * NXD * NXD];          // [3072,1024]
__device__ __half g_wT_proj[(size_t)NXD * NXD];              // [1024,1024]

__device__ __forceinline__ uint32_t smem_u32(const void* p) {
    uint32_t a;
    asm("{ .reg .u64 t; cvta.to.shared.u64 t, %1; cvt.u32.u64 %0, t; }"
        : "=r"(a) : "l"(p));
    return a;
}
__device__ __forceinline__ uint32_t packh2(float a, float b) {
    __half2 h = __floats2half2_rn(a, b);
    return *(uint32_t*)&h;
}
__device__ __forceinline__ void cp16(uint32_t dst, const void* src) {
    asm volatile("cp.async.cg.shared.global [%0], [%1], 16;"
                 :: "r"(dst), "l"(src) : "memory");
}
__device__ __forceinline__ void cp_commit() {
    asm volatile("cp.async.commit_group;" ::: "memory");
}
__device__ __forceinline__ void mma_f16(float* d,
    uint32_t a0, uint32_t a1, uint32_t a2, uint32_t a3,
    uint32_t b0, uint32_t b1)
{
    asm volatile(
        "mma.sync.aligned.m16n8k16.row.col.f32.f16.f16.f32 "
        "{%0,%1,%2,%3}, {%4,%5,%6,%7}, {%8,%9}, {%0,%1,%2,%3};"
        : "+f"(d[0]), "+f"(d[1]), "+f"(d[2]), "+f"(d[3])
        : "r"(a0), "r"(a1), "r"(a2), "r"(a3), "r"(b0), "r"(b1));
}
__device__ __forceinline__ void ldsm4(uint32_t* r, uint32_t addr) {
    asm volatile("ldmatrix.sync.aligned.m8n8.x4.shared.b16 {%0,%1,%2,%3}, [%4];"
                 : "=r"(r[0]), "=r"(r[1]), "=r"(r[2]), "=r"(r[3]) : "r"(addr));
}

// ---------------------------------------------------------------------------
// Fused prep: x->fp16 copy + both weight transposes (one launch).
// ---------------------------------------------------------------------------
__global__ void __launch_bounds__(256) prep_kernel(
    const float* __restrict__ x,
    const float* __restrict__ w_attn,
    const float* __restrict__ w_proj)
{
    const int bid = blockIdx.x;
    if (bid < 4096) {
        int i = bid * 256 + threadIdx.x;
        float4 v = ((const float4*)x)[i];
        uint2 o;
        o.x = packh2(v.x, v.y);
        o.y = packh2(v.z, v.w);
        ((uint2*)g_x)[i] = o;
        return;
    }
    __shared__ float tile[32][33];
    const float* src;  __half* dst;  int R, C, c0, r0;
    if (bid < 7168) {
        int b2 = bid - 4096;
        src = w_attn;  dst = g_wT_attn;  R = NXD;  C = 3 * NXD;
        c0 = (b2 % 96) * 32;  r0 = (b2 / 96) * 32;
    } else {
        int b2 = bid - 7168;
        src = w_proj;  dst = g_wT_proj;  R = NXD;  C = NXD;
        c0 = (b2 % 32) * 32;  r0 = (b2 / 32) * 32;
    }
    int tx = threadIdx.x & 31, ty = threadIdx.x >> 5;
#pragma unroll
    for (int i = 0; i < 32; i += 8)
        tile[ty + i][tx] = src[(size_t)(r0 + ty + i) * C + c0 + tx];
    __syncthreads();
#pragma unroll
    for (int i = 0; i < 32; i += 8)
        dst[(size_t)(c0 + ty + i) * R + r0 + tx] = __float2half(tile[tx][ty + i]);
}

// V transpose fp16: g_v [b,h,s,d] -> g_vT [b,h,d,s]
__global__ void __launch_bounds__(256) vtrans_kernel()
{
    __shared__ __half tile[32][33];
    int bh = blockIdx.z;
    int s0 = blockIdx.x * 32, d0 = blockIdx.y * 32;
    const __half* src = g_v + (size_t)bh * SEQ * HDIM;
    __half* dst = g_vT + (size_t)bh * SEQ * HDIM;
    int tx = threadIdx.x & 31, ty = threadIdx.x >> 5;
#pragma unroll
    for (int i = 0; i < 32; i += 8)
        tile[ty + i][tx] = src[(size_t)(s0 + ty + i) * HDIM + d0 + tx];
    __syncthreads();
#pragma unroll
    for (int i = 0; i < 32; i += 8)
        dst[(size_t)(d0 + ty + i) * SEQ + s0 + tx] = tile[tx][ty + i];
}

// ---------------------------------------------------------------------------
// fp16 mma.sync GEMM (fp32 accum), ldmatrix fragment loads.
// Block 128x128, BK=64, 8 warps (32x64), 3-stage cp.async, 2 CTAs/SM.
// ---------------------------------------------------------------------------
#define TLD2 36                          // u32 per smem row (72 halves, 144B)
#define STG32 (256 * TLD2)               // u32 per stage
#define GEMM_SMEM (3 * STG32 * 4)        // 110,592 B

__global__ void __launch_bounds__(256, 2) gemm_mma_kernel(
    const __half* __restrict__ A, const __half* __restrict__ BT,
    const float* __restrict__ bias, float* __restrict__ Cout,
    float* __restrict__ present, int mode)
{
    extern __shared__ uint32_t sm32[];

    const int t = threadIdx.x;
    const int lane = t & 31, w = t >> 5;
    const int wm = w >> 1, wn = w & 1;          // 4 x 2 warps, 32x64 each
    const int qr = lane >> 2, qc = lane & 3;
    const int m0 = blockIdx.y * 128;
    const int n0 = blockIdx.x * 128;

    uint32_t sa_[3], sb_[3];
#pragma unroll
    for (int s = 0; s < 3; s++) {
        sa_[s] = smem_u32(sm32 + s * STG32);
        sb_[s] = sa_[s] + 128 * TLD2 * 4;
    }

    // ldmatrix lane offsets (bytes), loop-invariant
    // A-type (m16k16 x4): lanes 0-15 -> rows 0-15 col 0; 16-31 -> rows 0-15 col+16B
    const uint32_t a_loff = ((wm * 32 + (lane & 15)) * TLD2 + ((lane >> 4) << 2)) * 4;
    // B-type (two n8k16 per x4): lanes 0-7 rows p*16+0-7 @k0; 8-15 same rows +16B;
    // 16-23 rows p*16+8-15 @k0; 24-31 +16B
    const uint32_t b_loff = ((wn * 64 + ((lane >> 4) << 3) + (lane & 7)) * TLD2
                             + (((lane >> 3) & 1) << 2)) * 4;

    float acc[2][8][4];
#pragma unroll
    for (int mt = 0; mt < 2; mt++)
#pragma unroll
        for (int nt = 0; nt < 8; nt++)
#pragma unroll
            for (int r = 0; r < 4; r++) acc[mt][nt][r] = 0.f;

#pragma unroll
    for (int s = 0; s < 2; s++) {
        const int k0 = s * 64;
#pragma unroll
        for (int i = 0; i < 4; i++) {
            int idx = t + i * 256;
            int row = idx >> 3, ch = idx & 7;
            cp16(sa_[s] + ((uint32_t)row * TLD2 + ch * 4) * 4,
                 A + (size_t)(m0 + row) * GK + k0 + ch * 8);
            cp16(sb_[s] + ((uint32_t)row * TLD2 + ch * 4) * 4,
                 BT + (size_t)(n0 + row) * GK + k0 + ch * 8);
        }
        cp_commit();
    }

    for (int kb = 0; kb < 16; kb++) {
        if (kb < 14)
            asm volatile("cp.async.wait_group 1;" ::: "memory");
        else
            asm volatile("cp.async.wait_group 0;" ::: "memory");
        __syncthreads();

        if (kb + 2 < 16) {
            const int s = (kb + 2) % 3;
            const int k0 = (kb + 2) * 64;
#pragma unroll
            for (int i = 0; i < 4; i++) {
                int idx = t + i * 256;
                int row = idx >> 3, ch = idx & 7;
                cp16(sa_[s] + ((uint32_t)row * TLD2 + ch * 4) * 4,
                     A + (size_t)(m0 + row) * GK + k0 + ch * 8);
                cp16(sb_[s] + ((uint32_t)row * TLD2 + ch * 4) * 4,
                     BT + (size_t)(n0 + row) * GK + k0 + ch * 8);
            }
            cp_commit();
        }

        const uint32_t a_addr = sa_[kb % 3] + a_loff;
        const uint32_t b_addr = sb_[kb % 3] + b_loff;
#pragma unroll
        for (int ks = 0; ks < 4; ks++) {        // 4 k16 steps, +32B each
            uint32_t af[2][4], bf[4][4];
            ldsm4(af[0], a_addr + ks * 32);
            ldsm4(af[1], a_addr + 16 * TLD2 * 4 + ks * 32);
#pragma unroll
            for (int p = 0; p < 4; p++)
                ldsm4(bf[p], b_addr + p * 16 * TLD2 * 4 + ks * 32);
#pragma unroll
            for (int mt = 0; mt < 2; mt++)
#pragma unroll
                for (int nt = 0; nt < 8; nt++)
                    mma_f16(acc[mt][nt], af[mt][0], af[mt][1], af[mt][2], af[mt][3],
                            bf[nt >> 1][(nt & 1) * 2], bf[nt >> 1][(nt & 1) * 2 + 1]);
        }
    }

#pragma unroll
    for (int mt = 0; mt < 2; mt++) {
#pragma unroll
        for (int nt = 0; nt < 8; nt++) {
            int row = m0 + wm * 32 + mt * 16 + qr;
            int col = n0 + wn * 64 + nt * 8 + qc * 2;
            float bv0 = bias[col], bv1 = bias[col + 1];
            float v00 = acc[mt][nt][0] + bv0, v01 = acc[mt][nt][1] + bv1;
            float v10 = acc[mt][nt][2] + bv0, v11 = acc[mt][nt][3] + bv1;
            if (mode == 1) {
                *(float2*)(Cout + (size_t)row * NXD + col) = make_float2(v00, v01);
                *(float2*)(Cout + (size_t)(row + 8) * NXD + col) = make_float2(v10, v11);
            } else {
                int sec = col >> 10;
                int hn = col & 1023;
                int h = hn >> 6, d = hn & 63;
                int b0_ = row >> 10, s0_ = row & 1023;
                size_t i0 = (((size_t)b0_ * NHEAD + h) * SEQ + s0_) * HDIM + d;
                int b1_ = (row + 8) >> 10, s1_ = (row + 8) & 1023;
                size_t i1 = (((size_t)b1_ * NHEAD + h) * SEQ + s1_) * HDIM + d;
                if (sec == 0) {
                    *(uint32_t*)(g_q + i0) = packh2(v00 * 0.125f, v01 * 0.125f);
                    *(uint32_t*)(g_q + i1) = packh2(v10 * 0.125f, v11 * 0.125f);
                } else if (sec == 1) {
                    *(float2*)(present + i0) = make_float2(v00, v01);
                    *(float2*)(present + i1) = make_float2(v10, v11);
                    *(uint32_t*)(g_k + i0) = packh2(v00, v01);
                    *(uint32_t*)(g_k + i1) = packh2(v10, v11);
                } else {
                    float* pv = present + (size_t)BATCH * NHEAD * SEQ * HDIM;
                    *(float2*)(pv + i0) = make_float2(v00, v01);
                    *(float2*)(pv + i1) = make_float2(v10, v11);
                    *(uint32_t*)(g_v + i0) = packh2(v00, v01);
                    *(uint32_t*)(g_v + i1) = packh2(v10, v11);
                }
            }
        }
    }
}

// ---------------------------------------------------------------------------
// Attention: fp16 mma.sync, ldmatrix frag loads, P register-resident,
// reversed q-tile order, 2 CTAs/SM.
// ---------------------------------------------------------------------------
#define ATTN_SMEM ((128 * TLD2 + 2 * 64 * TLD2 + 2 * 64 * TLD2) * 4)  // 55,296 B

__global__ void __launch_bounds__(256, 2) attn_mma_kernel()
{
    extern __shared__ uint32_t sma32[];
    uint32_t* Qs = sma32;                        // [128][36] (q, d) h2
    uint32_t* Ksb = Qs + 128 * TLD2;             // 2 x [64][36] (kpos, d) h2
    uint32_t* Vtb = Ksb + 2 * 64 * TLD2;         // 2 x [64][36] (d, kpos) h2

    const int t = threadIdx.x;
    const int lane = t & 31, w = t >> 5;
    const int qr = lane >> 2, qc = lane & 3;
    const int xr = (int)gridDim.x - 1 - (int)blockIdx.x;   // reversed tile id
    const int q0 = xr * 128;
    const int h = blockIdx.y;
    const int b = blockIdx.z;

    const __half* qptr = g_q + ((size_t)b * NHEAD + h) * SEQ * HDIM;
    const __half* kptr = g_k + ((size_t)b * NHEAD + h) * SEQ * HDIM;
    const __half* vtp  = g_vT + ((size_t)b * NHEAD + h) * SEQ * HDIM;

    const uint32_t qs_a = smem_u32(Qs);
    const uint32_t ks_a[2] = { smem_u32(Ksb), smem_u32(Ksb + 64 * TLD2) };
    const uint32_t vs_a[2] = { smem_u32(Vtb), smem_u32(Vtb + 64 * TLD2) };

    const int wrow = w * 16;
    // ldmatrix lane offsets (bytes)
    const uint32_t qa_loff = ((wrow + (lane & 15)) * TLD2 + ((lane >> 4) << 2)) * 4;
    const uint32_t kb_loff = ((((lane >> 4) << 3) + (lane & 7)) * TLD2
                              + (((lane >> 3) & 1) << 2)) * 4;

#pragma unroll
    for (int i = 0; i < 4; i++) {
        int c = t + i * 256;
        int row = c >> 3, ch = c & 7;
        cp16(qs_a + ((uint32_t)row * TLD2 + ch * 4) * 4,
             qptr + (size_t)(q0 + row) * HDIM + ch * 8);
    }
#pragma unroll
    for (int i = 0; i < 2; i++) {
        int c = t + i * 256;
        int row = c >> 3, ch = c & 7;
        uint32_t off = ((uint32_t)row * TLD2 + ch * 4) * 4;
        cp16(ks_a[0] + off, kptr + (size_t)row * HDIM + ch * 8);
        cp16(vs_a[0] + off, vtp + (size_t)row * SEQ + ch * 8);
    }
    cp_commit();

    float oacc[8][4];
#pragma unroll
    for (int nt = 0; nt < 8; nt++)
#pragma unroll
        for (int r = 0; r < 4; r++) oacc[nt][r] = 0.f;
    float m0 = -1e30f, m1 = -1e30f, l0 = 0.f, l1 = 0.f;

    const int qg0 = q0 + wrow + qr;
    const int qg1 = qg0 + 8;
    const int qmax = q0 + wrow + 15;
    const int nj = xr * 2 + 2;

    asm volatile("cp.async.wait_group 0;" ::: "memory");
    __syncthreads();
    uint32_t qf[4][4];
#pragma unroll
    for (int ks = 0; ks < 4; ks++)
        ldsm4(qf[ks], qs_a + qa_loff + ks * 32);

    for (int jt = 0; jt < nj; jt++) {
        const int j0 = jt * 64;
        if (jt > 0) {
            asm volatile("cp.async.wait_group 0;" ::: "memory");
            __syncthreads();
        }
        if (jt + 1 < nj) {
            const int buf = (jt + 1) & 1;
            const int jr = (jt + 1) * 64;
#pragma unroll
            for (int i = 0; i < 2; i++) {
                int c = t + i * 256;
                int row = c >> 3, ch = c & 7;
                uint32_t off = ((uint32_t)row * TLD2 + ch * 4) * 4;
                cp16(ks_a[buf] + off, kptr + (size_t)(jr + row) * HDIM + ch * 8);
                cp16(vs_a[buf] + off, vtp + (size_t)row * SEQ + jr + ch * 8);
            }
            cp_commit();
        }
        if (j0 > qmax) continue;

        const uint32_t k_addr = ks_a[jt & 1] + kb_loff;
        const uint32_t v_addr = vs_a[jt & 1] + kb_loff;

        // ---- S = Q @ K^T ----
        float sacc[8][4];
#pragma unroll
        for (int nt = 0; nt < 8; nt++)
#pragma unroll
            for (int r = 0; r < 4; r++) sacc[nt][r] = 0.f;

#pragma unroll
        for (int ks = 0; ks < 4; ks++) {
            uint32_t kf[4][4];
#pragma unroll
            for (int p = 0; p < 4; p++)
                ldsm4(kf[p], k_addr + p * 16 * TLD2 * 4 + ks * 32);
#pragma unroll
            for (int nt = 0; nt < 8; nt++)
                mma_f16(sacc[nt], qf[ks][0], qf[ks][1], qf[ks][2], qf[ks][3],
                        kf[nt >> 1][(nt & 1) * 2], kf[nt >> 1][(nt & 1) * 2 + 1]);
        }

        // ---- causal mask + row max ----
        float rx0 = -1e30f, rx1 = -1e30f;
#pragma unroll
        for (int nt = 0; nt < 8; nt++) {
            int kg = j0 + nt * 8 + qc * 2;
            if (kg > qg0)     sacc[nt][0] = -1e30f;
            if (kg + 1 > qg0) sacc[nt][1] = -1e30f;
            if (kg > qg1)     sacc[nt][2] = -1e30f;
            if (kg + 1 > qg1) sacc[nt][3] = -1e30f;
            rx0 = fmaxf(rx0, fmaxf(sacc[nt][0], sacc[nt][1]));
            rx1 = fmaxf(rx1, fmaxf(sacc[nt][2], sacc[nt][3]));
        }
        rx0 = fmaxf(rx0, __shfl_xor_sync(0xffffffffu, rx0, 1));
        rx0 = fmaxf(rx0, __shfl_xor_sync(0xffffffffu, rx0, 2));
        rx1 = fmaxf(rx1, __shfl_xor_sync(0xffffffffu, rx1, 1));
        rx1 = fmaxf(rx1, __shfl_xor_sync(0xffffffffu, rx1, 2));

        float nm0 = fmaxf(m0, rx0), nm1 = fmaxf(m1, rx1);
        float cr0 = __expf(m0 - nm0), cr1 = __expf(m1 - nm1);

        // ---- exp, row sum, pack P (register-resident) ----
        float rs0 = 0.f, rs1 = 0.f;
        uint32_t plo[8], phi[8];
#pragma unroll
        for (int nt = 0; nt < 8; nt++) {
            float p00 = __expf(sacc[nt][0] - nm0);
            float p01 = __expf(sacc[nt][1] - nm0);
            float p10 = __expf(sacc[nt][2] - nm1);
            float p11 = __expf(sacc[nt][3] - nm1);
            rs0 += p00 + p01;
            rs1 += p10 + p11;
            plo[nt] = packh2(p00, p01);
            phi[nt] = packh2(p10, p11);
        }
        rs0 += __shfl_xor_sync(0xffffffffu, rs0, 1);
        rs0 += __shfl_xor_sync(0xffffffffu, rs0, 2);
        rs1 += __shfl_xor_sync(0xffffffffu, rs1, 1);
        rs1 += __shfl_xor_sync(0xffffffffu, rs1, 2);

        l0 = l0 * cr0 + rs0;  m0 = nm0;
        l1 = l1 * cr1 + rs1;  m1 = nm1;
#pragma unroll
        for (int nt = 0; nt < 8; nt++) {
            oacc[nt][0] *= cr0;  oacc[nt][1] *= cr0;
            oacc[nt][2] *= cr1;  oacc[nt][3] *= cr1;
        }

        // ---- O += P @ V ----
#pragma unroll
        for (int j = 0; j < 4; j++) {
            uint32_t vf[4][4];
#pragma unroll
            for (int p = 0; p < 4; p++)
                ldsm4(vf[p], v_addr + p * 16 * TLD2 * 4 + j * 32);
            uint32_t a0 = plo[2 * j], a1 = phi[2 * j];
            uint32_t a2 = plo[2 * j + 1], a3 = phi[2 * j + 1];
#pragma unroll
            for (int nt = 0; nt < 8; nt++)
                mma_f16(oacc[nt], a0, a1, a2, a3,
                        vf[nt >> 1][(nt & 1) * 2], vf[nt >> 1][(nt & 1) * 2 + 1]);
        }
    }

    __syncthreads();
    float inv0 = 1.f / l0, inv1 = 1.f / l1;
#pragma unroll
    for (int nt = 0; nt < 8; nt++) {
        Qs[(wrow + qr) * TLD2 + nt * 4 + qc] =
            packh2(oacc[nt][0] * inv0, oacc[nt][1] * inv0);
        Qs[(wrow + qr + 8) * TLD2 + nt * 4 + qc] =
            packh2(oacc[nt][2] * inv1, oacc[nt][3] * inv1);
    }
    __syncthreads();
    for (int idx = t; idx < 128 * 32; idx += 256) {
        int row = idx >> 5, c2 = idx & 31;
        *(uint32_t*)(g_a + ((size_t)b * SEQ + q0 + row) * NXD + h * HDIM + c2 * 2) =
            Qs[row * TLD2 + c2];
    }
}

// ---------------------------------------------------------------------------
extern "C" void kernel_launch(void* const* d_in, const int* in_sizes, int n_in,
                              void* d_out, int out_size)
{
    const float* x      = (const float*)d_in[0];
    const float* w_attn = (const float*)d_in[1];
    const float* b_attn = (const float*)d_in[2];
    const float* w_proj = (const float*)d_in[3];
    const float* b_proj = (const float*)d_in[4];

    float* out = (float*)d_out;
    float* present = out + (size_t)BATCH * SEQ * NXD;  // (2,B,NH,S,HD)

    cudaFuncSetAttribute(gemm_mma_kernel,
                         cudaFuncAttributeMaxDynamicSharedMemorySize, GEMM_SMEM);
    cudaFuncSetAttribute(attn_mma_kernel,
                         cudaFuncAttributeMaxDynamicSharedMemorySize, ATTN_SMEM);

    __half* wT_attn;  cudaGetSymbolAddress((void**)&wT_attn, g_wT_attn);
    __half* wT_proj;  cudaGetSymbolAddress((void**)&wT_proj, g_wT_proj);
    __half* a_ptr;    cudaGetSymbolAddress((void**)&a_ptr, g_a);
    __half* x_ptr;    cudaGetSymbolAddress((void**)&x_ptr, g_x);

    prep_kernel<<<8192, 256>>>(x, w_attn, w_proj);

    gemm_mma_kernel<<<dim3(3 * NXD / 128, BATCH * SEQ / 128), 256, GEMM_SMEM>>>(
        x_ptr, wT_attn, b_attn, nullptr, present, 0);

    vtrans_kernel<<<dim3(SEQ / 32, HDIM / 32, BATCH * NHEAD), 256>>>();

    attn_mma_kernel<<<dim3(SEQ / 128, NHEAD, BATCH), 256, ATTN_SMEM>>>();

    gemm_mma_kernel<<<dim3(NXD / 128, BATCH * SEQ / 128), 256, GEMM_SMEM>>>(
        a_ptr, wT_proj, b_proj, out, nullptr, 1);
}

// round 14
// speedup vs baseline: 1.1191x; 1.0555x over previous
#include <cuda_runtime.h>
#include <cuda_fp16.h>
#include <cstdint>

#define BATCH 4
#define SEQ   1024
#define NXD   1024
#define NHEAD 16
#define HDIM  64
#define GK    1024

// Scratch (allocation-free rule: __device__ globals) — fp16 internals
__device__ __half g_q[(size_t)BATCH * NHEAD * SEQ * HDIM];   // pre-scaled by 0.125*log2(e)
__device__ __half g_k[(size_t)BATCH * NHEAD * SEQ * HDIM];
__device__ __half g_v[(size_t)BATCH * NHEAD * SEQ * HDIM];   // [b,h,s,d]
__device__ __half g_a[(size_t)BATCH * SEQ * NXD];
__device__ __half g_x[(size_t)BATCH * SEQ * NXD];
__device__ __half g_wT_attn[(size_t)3 * NXD * NXD];          // [3072,1024]
__device__ __half g_wT_proj[(size_t)NXD * NXD];              // [1024,1024]

__device__ __forceinline__ uint32_t smem_u32(const void* p) {
    uint32_t a;
    asm("{ .reg .u64 t; cvta.to.shared.u64 t, %1; cvt.u32.u64 %0, t; }"
        : "=r"(a) : "l"(p));
    return a;
}
__device__ __forceinline__ uint32_t packh2(float a, float b) {
    __half2 h = __floats2half2_rn(a, b);
    return *(uint32_t*)&h;
}
__device__ __forceinline__ void cp16(uint32_t dst, const void* src) {
    asm volatile("cp.async.cg.shared.global [%0], [%1], 16;"
                 :: "r"(dst), "l"(src) : "memory");
}
__device__ __forceinline__ void cp_commit() {
    asm volatile("cp.async.commit_group;" ::: "memory");
}
__device__ __forceinline__ void mma_f16(float* d,
    uint32_t a0, uint32_t a1, uint32_t a2, uint32_t a3,
    uint32_t b0, uint32_t b1)
{
    asm volatile(
        "mma.sync.aligned.m16n8k16.row.col.f32.f16.f16.f32 "
        "{%0,%1,%2,%3}, {%4,%5,%6,%7}, {%8,%9}, {%0,%1,%2,%3};"
        : "+f"(d[0]), "+f"(d[1]), "+f"(d[2]), "+f"(d[3])
        : "r"(a0), "r"(a1), "r"(a2), "r"(a3), "r"(b0), "r"(b1));
}
__device__ __forceinline__ void ldsm4(uint32_t* r, uint32_t addr) {
    asm volatile("ldmatrix.sync.aligned.m8n8.x4.shared.b16 {%0,%1,%2,%3}, [%4];"
                 : "=r"(r[0]), "=r"(r[1]), "=r"(r[2]), "=r"(r[3]) : "r"(addr));
}
__device__ __forceinline__ void ldsm4t(uint32_t* r, uint32_t addr) {
    asm volatile("ldmatrix.sync.aligned.m8n8.x4.trans.shared.b16 {%0,%1,%2,%3}, [%4];"
                 : "=r"(r[0]), "=r"(r[1]), "=r"(r[2]), "=r"(r[3]) : "r"(addr));
}

// q pre-scale: (1/sqrt(64)) * log2(e)  -> softmax in exp2 domain
#define QSCALE 0.18033688011112042f

// ---------------------------------------------------------------------------
// Fused prep: x->fp16 copy + both weight transposes (one launch).
// ---------------------------------------------------------------------------
__global__ void __launch_bounds__(256) prep_kernel(
    const float* __restrict__ x,
    const float* __restrict__ w_attn,
    const float* __restrict__ w_proj)
{
    const int bid = blockIdx.x;
    if (bid < 4096) {
        int i = bid * 256 + threadIdx.x;
        float4 v = ((const float4*)x)[i];
        uint2 o;
        o.x = packh2(v.x, v.y);
        o.y = packh2(v.z, v.w);
        ((uint2*)g_x)[i] = o;
        return;
    }
    __shared__ float tile[32][33];
    const float* src;  __half* dst;  int R, C, c0, r0;
    if (bid < 7168) {
        int b2 = bid - 4096;
        src = w_attn;  dst = g_wT_attn;  R = NXD;  C = 3 * NXD;
        c0 = (b2 % 96) * 32;  r0 = (b2 / 96) * 32;
    } else {
        int b2 = bid - 7168;
        src = w_proj;  dst = g_wT_proj;  R = NXD;  C = NXD;
        c0 = (b2 % 32) * 32;  r0 = (b2 / 32) * 32;
    }
    int tx = threadIdx.x & 31, ty = threadIdx.x >> 5;
#pragma unroll
    for (int i = 0; i < 32; i += 8)
        tile[ty + i][tx] = src[(size_t)(r0 + ty + i) * C + c0 + tx];
    __syncthreads();
#pragma unroll
    for (int i = 0; i < 32; i += 8)
        dst[(size_t)(c0 + ty + i) * R + r0 + tx] = __float2half(tile[tx][ty + i]);
}

// ---------------------------------------------------------------------------
// fp16 mma.sync GEMM (fp32 accum), ldmatrix frag loads — unchanged from R13.
// ---------------------------------------------------------------------------
#define TLD2 36                          // u32 per smem row (72 halves, 144B)
#define STG32 (256 * TLD2)
#define GEMM_SMEM (3 * STG32 * 4)        // 110,592 B

__global__ void __launch_bounds__(256, 2) gemm_mma_kernel(
    const __half* __restrict__ A, const __half* __restrict__ BT,
    const float* __restrict__ bias, float* __restrict__ Cout,
    float* __restrict__ present, int mode)
{
    extern __shared__ uint32_t sm32[];

    const int t = threadIdx.x;
    const int lane = t & 31, w = t >> 5;
    const int wm = w >> 1, wn = w & 1;
    const int qr = lane >> 2, qc = lane & 3;
    const int m0 = blockIdx.y * 128;
    const int n0 = blockIdx.x * 128;

    uint32_t sa_[3], sb_[3];
#pragma unroll
    for (int s = 0; s < 3; s++) {
        sa_[s] = smem_u32(sm32 + s * STG32);
        sb_[s] = sa_[s] + 128 * TLD2 * 4;
    }

    const uint32_t a_loff = ((wm * 32 + (lane & 15)) * TLD2 + ((lane >> 4) << 2)) * 4;
    const uint32_t b_loff = ((wn * 64 + ((lane >> 4) << 3) + (lane & 7)) * TLD2
                             + (((lane >> 3) & 1) << 2)) * 4;

    float acc[2][8][4];
#pragma unroll
    for (int mt = 0; mt < 2; mt++)
#pragma unroll
        for (int nt = 0; nt < 8; nt++)
#pragma unroll
            for (int r = 0; r < 4; r++) acc[mt][nt][r] = 0.f;

#pragma unroll
    for (int s = 0; s < 2; s++) {
        const int k0 = s * 64;
#pragma unroll
        for (int i = 0; i < 4; i++) {
            int idx = t + i * 256;
            int row = idx >> 3, ch = idx & 7;
            cp16(sa_[s] + ((uint32_t)row * TLD2 + ch * 4) * 4,
                 A + (size_t)(m0 + row) * GK + k0 + ch * 8);
            cp16(sb_[s] + ((uint32_t)row * TLD2 + ch * 4) * 4,
                 BT + (size_t)(n0 + row) * GK + k0 + ch * 8);
        }
        cp_commit();
    }

    for (int kb = 0; kb < 16; kb++) {
        if (kb < 14)
            asm volatile("cp.async.wait_group 1;" ::: "memory");
        else
            asm volatile("cp.async.wait_group 0;" ::: "memory");
        __syncthreads();

        if (kb + 2 < 16) {
            const int s = (kb + 2) % 3;
            const int k0 = (kb + 2) * 64;
#pragma unroll
            for (int i = 0; i < 4; i++) {
                int idx = t + i * 256;
                int row = idx >> 3, ch = idx & 7;
                cp16(sa_[s] + ((uint32_t)row * TLD2 + ch * 4) * 4,
                     A + (size_t)(m0 + row) * GK + k0 + ch * 8);
                cp16(sb_[s] + ((uint32_t)row * TLD2 + ch * 4) * 4,
                     BT + (size_t)(n0 + row) * GK + k0 + ch * 8);
            }
            cp_commit();
        }

        const uint32_t a_addr = sa_[kb % 3] + a_loff;
        const uint32_t b_addr = sb_[kb % 3] + b_loff;
#pragma unroll
        for (int ks = 0; ks < 4; ks++) {
            uint32_t af[2][4], bf[4][4];
            ldsm4(af[0], a_addr + ks * 32);
            ldsm4(af[1], a_addr + 16 * TLD2 * 4 + ks * 32);
#pragma unroll
            for (int p = 0; p < 4; p++)
                ldsm4(bf[p], b_addr + p * 16 * TLD2 * 4 + ks * 32);
#pragma unroll
            for (int mt = 0; mt < 2; mt++)
#pragma unroll
                for (int nt = 0; nt < 8; nt++)
                    mma_f16(acc[mt][nt], af[mt][0], af[mt][1], af[mt][2], af[mt][3],
                            bf[nt >> 1][(nt & 1) * 2], bf[nt >> 1][(nt & 1) * 2 + 1]);
        }
    }

#pragma unroll
    for (int mt = 0; mt < 2; mt++) {
#pragma unroll
        for (int nt = 0; nt < 8; nt++) {
            int row = m0 + wm * 32 + mt * 16 + qr;
            int col = n0 + wn * 64 + nt * 8 + qc * 2;
            float bv0 = bias[col], bv1 = bias[col + 1];
            float v00 = acc[mt][nt][0] + bv0, v01 = acc[mt][nt][1] + bv1;
            float v10 = acc[mt][nt][2] + bv0, v11 = acc[mt][nt][3] + bv1;
            if (mode == 1) {
                *(float2*)(Cout + (size_t)row * NXD + col) = make_float2(v00, v01);
                *(float2*)(Cout + (size_t)(row + 8) * NXD + col) = make_float2(v10, v11);
            } else {
                int sec = col >> 10;
                int hn = col & 1023;
                int h = hn >> 6, d = hn & 63;
                int b0_ = row >> 10, s0_ = row & 1023;
                size_t i0 = (((size_t)b0_ * NHEAD + h) * SEQ + s0_) * HDIM + d;
                int b1_ = (row + 8) >> 10, s1_ = (row + 8) & 1023;
                size_t i1 = (((size_t)b1_ * NHEAD + h) * SEQ + s1_) * HDIM + d;
                if (sec == 0) {          // q -> scratch (exp2-domain scale)
                    *(uint32_t*)(g_q + i0) = packh2(v00 * QSCALE, v01 * QSCALE);
                    *(uint32_t*)(g_q + i1) = packh2(v10 * QSCALE, v11 * QSCALE);
                } else if (sec == 1) {
                    *(float2*)(present + i0) = make_float2(v00, v01);
                    *(float2*)(present + i1) = make_float2(v10, v11);
                    *(uint32_t*)(g_k + i0) = packh2(v00, v01);
                    *(uint32_t*)(g_k + i1) = packh2(v10, v11);
                } else {
                    float* pv = present + (size_t)BATCH * NHEAD * SEQ * HDIM;
                    *(float2*)(pv + i0) = make_float2(v00, v01);
                    *(float2*)(pv + i1) = make_float2(v10, v11);
                    *(uint32_t*)(g_v + i0) = packh2(v00, v01);
                    *(uint32_t*)(g_v + i1) = packh2(v10, v11);
                }
            }
        }
    }
}

// ---------------------------------------------------------------------------
// Attention: fp16 mma.sync, ldmatrix (V via ldmatrix.trans — no g_vT),
// exp2-domain softmax, diagonal-only masking, reversed q-tile order, 2 CTA/SM.
// ---------------------------------------------------------------------------
#define ATTN_SMEM ((128 * TLD2 + 2 * 64 * TLD2 + 2 * 64 * TLD2) * 4)  // 55,296 B

__global__ void __launch_bounds__(256, 2) attn_mma_kernel()
{
    extern __shared__ uint32_t sma32[];
    uint32_t* Qs = sma32;                        // [128][36] (q, d) h2
    uint32_t* Ksb = Qs + 128 * TLD2;             // 2 x [64][36] (kpos, d) h2
    uint32_t* Vsb = Ksb + 2 * 64 * TLD2;         // 2 x [64][36] (kpos, d) h2

    const int t = threadIdx.x;
    const int lane = t & 31, w = t >> 5;
    const int qr = lane >> 2, qc = lane & 3;
    const int xr = (int)gridDim.x - 1 - (int)blockIdx.x;   // reversed tile id
    const int q0 = xr * 128;
    const int h = blockIdx.y;
    const int b = blockIdx.z;

    const __half* qptr = g_q + ((size_t)b * NHEAD + h) * SEQ * HDIM;
    const __half* kptr = g_k + ((size_t)b * NHEAD + h) * SEQ * HDIM;
    const __half* vptr = g_v + ((size_t)b * NHEAD + h) * SEQ * HDIM;

    const uint32_t qs_a = smem_u32(Qs);
    const uint32_t ks_a[2] = { smem_u32(Ksb), smem_u32(Ksb + 64 * TLD2) };
    const uint32_t vs_a[2] = { smem_u32(Vsb), smem_u32(Vsb + 64 * TLD2) };

    const int wrow = w * 16;
    // ldmatrix lane offsets (bytes)
    const uint32_t qa_loff = ((wrow + (lane & 15)) * TLD2 + ((lane >> 4) << 2)) * 4;
    const uint32_t kb_loff = ((((lane >> 4) << 3) + (lane & 7)) * TLD2
                              + (((lane >> 3) & 1) << 2)) * 4;
    // V trans: lanes 0-7 kpos 0-7 d0; 8-15 kpos 8-15 d0; 16-23 kpos 0-7 d+8; 24-31 kpos 8-15 d+8
    const uint32_t vt_loff = (((((lane >> 3) & 1) << 3) + (lane & 7)) * TLD2
                              + ((lane >> 4) << 2)) * 4;

#pragma unroll
    for (int i = 0; i < 4; i++) {
        int c = t + i * 256;
        int row = c >> 3, ch = c & 7;
        cp16(qs_a + ((uint32_t)row * TLD2 + ch * 4) * 4,
             qptr + (size_t)(q0 + row) * HDIM + ch * 8);
    }
#pragma unroll
    for (int i = 0; i < 2; i++) {
        int c = t + i * 256;
        int row = c >> 3, ch = c & 7;
        uint32_t off = ((uint32_t)row * TLD2 + ch * 4) * 4;
        cp16(ks_a[0] + off, kptr + (size_t)row * HDIM + ch * 8);
        cp16(vs_a[0] + off, vptr + (size_t)row * HDIM + ch * 8);
    }
    cp_commit();

    float oacc[8][4];
#pragma unroll
    for (int nt = 0; nt < 8; nt++)
#pragma unroll
        for (int r = 0; r < 4; r++) oacc[nt][r] = 0.f;
    float m0 = -1e30f, m1 = -1e30f, l0 = 0.f, l1 = 0.f;

    const int qg0 = q0 + wrow + qr;
    const int qg1 = qg0 + 8;
    const int qmax = q0 + wrow + 15;
    const int nj = xr * 2 + 2;

    asm volatile("cp.async.wait_group 0;" ::: "memory");
    __syncthreads();
    uint32_t qf[4][4];
#pragma unroll
    for (int ks = 0; ks < 4; ks++)
        ldsm4(qf[ks], qs_a + qa_loff + ks * 32);

    for (int jt = 0; jt < nj; jt++) {
        const int j0 = jt * 64;
        if (jt > 0) {
            asm volatile("cp.async.wait_group 0;" ::: "memory");
            __syncthreads();
        }
        if (jt + 1 < nj) {
            const int buf = (jt + 1) & 1;
            const int jr = (jt + 1) * 64;
#pragma unroll
            for (int i = 0; i < 2; i++) {
                int c = t + i * 256;
                int row = c >> 3, ch = c & 7;
                uint32_t off = ((uint32_t)row * TLD2 + ch * 4) * 4;
                cp16(ks_a[buf] + off, kptr + (size_t)(jr + row) * HDIM + ch * 8);
                cp16(vs_a[buf] + off, vptr + (size_t)(jr + row) * HDIM + ch * 8);
            }
            cp_commit();
        }
        if (j0 > qmax) continue;

        const uint32_t k_addr = ks_a[jt & 1] + kb_loff;
        const uint32_t v_addr = vs_a[jt & 1] + vt_loff;

        // ---- S = Q @ K^T ----
        float sacc[8][4];
#pragma unroll
        for (int nt = 0; nt < 8; nt++)
#pragma unroll
            for (int r = 0; r < 4; r++) sacc[nt][r] = 0.f;

#pragma unroll
        for (int ks = 0; ks < 4; ks++) {
            uint32_t kf[4][4];
#pragma unroll
            for (int p = 0; p < 4; p++)
                ldsm4(kf[p], k_addr + p * 16 * TLD2 * 4 + ks * 32);
#pragma unroll
            for (int nt = 0; nt < 8; nt++)
                mma_f16(sacc[nt], qf[ks][0], qf[ks][1], qf[ks][2], qf[ks][3],
                        kf[nt >> 1][(nt & 1) * 2], kf[nt >> 1][(nt & 1) * 2 + 1]);
        }

        // ---- causal mask (diagonal tiles only) + row max ----
        float rx0 = -1e30f, rx1 = -1e30f;
        if (j0 + 63 > q0 + wrow) {           // partially-masked tile for this warp
#pragma unroll
            for (int nt = 0; nt < 8; nt++) {
                int kg = j0 + nt * 8 + qc * 2;
                if (kg > qg0)     sacc[nt][0] = -1e30f;
                if (kg + 1 > qg0) sacc[nt][1] = -1e30f;
                if (kg > qg1)     sacc[nt][2] = -1e30f;
                if (kg + 1 > qg1) sacc[nt][3] = -1e30f;
            }
        }
#pragma unroll
        for (int nt = 0; nt < 8; nt++) {
            rx0 = fmaxf(rx0, fmaxf(sacc[nt][0], sacc[nt][1]));
            rx1 = fmaxf(rx1, fmaxf(sacc[nt][2], sacc[nt][3]));
        }
        rx0 = fmaxf(rx0, __shfl_xor_sync(0xffffffffu, rx0, 1));
        rx0 = fmaxf(rx0, __shfl_xor_sync(0xffffffffu, rx0, 2));
        rx1 = fmaxf(rx1, __shfl_xor_sync(0xffffffffu, rx1, 1));
        rx1 = fmaxf(rx1, __shfl_xor_sync(0xffffffffu, rx1, 2));

        float nm0 = fmaxf(m0, rx0), nm1 = fmaxf(m1, rx1);
        float cr0 = exp2f(m0 - nm0), cr1 = exp2f(m1 - nm1);

        // ---- exp2, row sum, pack P (register-resident) ----
        float rs0 = 0.f, rs1 = 0.f;
        uint32_t plo[8], phi[8];
#pragma unroll
        for (int nt = 0; nt < 8; nt++) {
            float p00 = exp2f(sacc[nt][0] - nm0);
            float p01 = exp2f(sacc[nt][1] - nm0);
            float p10 = exp2f(sacc[nt][2] - nm1);
            float p11 = exp2f(sacc[nt][3] - nm1);
            rs0 += p00 + p01;
            rs1 += p10 + p11;
            plo[nt] = packh2(p00, p01);
            phi[nt] = packh2(p10, p11);
        }
        rs0 += __shfl_xor_sync(0xffffffffu, rs0, 1);
        rs0 += __shfl_xor_sync(0xffffffffu, rs0, 2);
        rs1 += __shfl_xor_sync(0xffffffffu, rs1, 1);
        rs1 += __shfl_xor_sync(0xffffffffu, rs1, 2);

        l0 = l0 * cr0 + rs0;  m0 = nm0;
        l1 = l1 * cr1 + rs1;  m1 = nm1;
#pragma unroll
        for (int nt = 0; nt < 8; nt++) {
            oacc[nt][0] *= cr0;  oacc[nt][1] *= cr0;
            oacc[nt][2] *= cr1;  oacc[nt][3] *= cr1;
        }

        // ---- O += P @ V (V frags via ldmatrix.trans from (kpos,d) tile) ----
#pragma unroll
        for (int j = 0; j < 4; j++) {
            uint32_t vf[4][4];
#pragma unroll
            for (int p = 0; p < 4; p++)
                ldsm4t(vf[p], v_addr + j * 16 * TLD2 * 4 + p * 32);
            uint32_t a0 = plo[2 * j], a1 = phi[2 * j];
            uint32_t a2 = plo[2 * j + 1], a3 = phi[2 * j + 1];
#pragma unroll
            for (int nt = 0; nt < 8; nt++)
                mma_f16(oacc[nt], a0, a1, a2, a3,
                        vf[nt >> 1][(nt & 1) * 2], vf[nt >> 1][(nt & 1) * 2 + 1]);
        }
    }

    __syncthreads();
    float inv0 = 1.f / l0, inv1 = 1.f / l1;
#pragma unroll
    for (int nt = 0; nt < 8; nt++) {
        Qs[(wrow + qr) * TLD2 + nt * 4 + qc] =
            packh2(oacc[nt][0] * inv0, oacc[nt][1] * inv0);
        Qs[(wrow + qr + 8) * TLD2 + nt * 4 + qc] =
            packh2(oacc[nt][2] * inv1, oacc[nt][3] * inv1);
    }
    __syncthreads();
    for (int idx = t; idx < 128 * 32; idx += 256) {
        int row = idx >> 5, c2 = idx & 31;
        *(uint32_t*)(g_a + ((size_t)b * SEQ + q0 + row) * NXD + h * HDIM + c2 * 2) =
            Qs[row * TLD2 + c2];
    }
}

// ---------------------------------------------------------------------------
extern "C" void kernel_launch(void* const* d_in, const int* in_sizes, int n_in,
                              void* d_out, int out_size)
{
    const float* x      = (const float*)d_in[0];
    const float* w_attn = (const float*)d_in[1];
    const float* b_attn = (const float*)d_in[2];
    const float* w_proj = (const float*)d_in[3];
    const float* b_proj = (const float*)d_in[4];

    float* out = (float*)d_out;
    float* present = out + (size_t)BATCH * SEQ * NXD;  // (2,B,NH,S,HD)

    cudaFuncSetAttribute(gemm_mma_kernel,
                         cudaFuncAttributeMaxDynamicSharedMemorySize, GEMM_SMEM);
    cudaFuncSetAttribute(attn_mma_kernel,
                         cudaFuncAttributeMaxDynamicSharedMemorySize, ATTN_SMEM);

    __half* wT_attn;  cudaGetSymbolAddress((void**)&wT_attn, g_wT_attn);
    __half* wT_proj;  cudaGetSymbolAddress((void**)&wT_proj, g_wT_proj);
    __half* a_ptr;    cudaGetSymbolAddress((void**)&a_ptr, g_a);
    __half* x_ptr;    cudaGetSymbolAddress((void**)&x_ptr, g_x);

    prep_kernel<<<8192, 256>>>(x, w_attn, w_proj);

    gemm_mma_kernel<<<dim3(3 * NXD / 128, BATCH * SEQ / 128), 256, GEMM_SMEM>>>(
        x_ptr, wT_attn, b_attn, nullptr, present, 0);

    attn_mma_kernel<<<dim3(SEQ / 128, NHEAD, BATCH), 256, ATTN_SMEM>>>();

    gemm_mma_kernel<<<dim3(NXD / 128, BATCH * SEQ / 128), 256, GEMM_SMEM>>>(
        a_ptr, wT_proj, b_proj, out, nullptr, 1);
}

// round 15
// speedup vs baseline: 1.1707x; 1.0461x over previous
#include <cuda_runtime.h>
#include <cuda_fp16.h>
#include <cstdint>

#define BATCH 4
#define SEQ   1024
#define NXD   1024
#define NHEAD 16
#define HDIM  64
#define GK    1024

// Scratch (allocation-free rule: __device__ globals) — fp16 internals
__device__ __half g_q[(size_t)BATCH * NHEAD * SEQ * HDIM];   // pre-scaled by 0.125*log2(e)
__device__ __half g_k[(size_t)BATCH * NHEAD * SEQ * HDIM];
__device__ __half g_v[(size_t)BATCH * NHEAD * SEQ * HDIM];   // [b,h,s,d]
__device__ __half g_a[(size_t)BATCH * SEQ * NXD];
__device__ __half g_x[(size_t)BATCH * SEQ * NXD];
__device__ __half g_wT_attn[(size_t)3 * NXD * NXD];          // [3072,1024]
__device__ __half g_wT_proj[(size_t)NXD * NXD];              // [1024,1024]

// work-queue state (re-zeroed by prep each launch)
__device__ int g_cursor;
__device__ int g_qkv_done[32];    // per (b*8 + sblock128), target 24
__device__ int g_attn_done[32];   // per (b*8 + qtile128), target 16

#define N_QKV  768
#define N_ATTN 512
#define N_ITEMS 1536

__device__ __forceinline__ uint32_t smem_u32(const void* p) {
    uint32_t a;
    asm("{ .reg .u64 t; cvta.to.shared.u64 t, %1; cvt.u32.u64 %0, t; }"
        : "=r"(a) : "l"(p));
    return a;
}
__device__ __forceinline__ uint32_t packh2(float a, float b) {
    __half2 h = __floats2half2_rn(a, b);
    return *(uint32_t*)&h;
}
__device__ __forceinline__ void cp16(uint32_t dst, const void* src) {
    asm volatile("cp.async.cg.shared.global [%0], [%1], 16;"
                 :: "r"(dst), "l"(src) : "memory");
}
__device__ __forceinline__ void cp_commit() {
    asm volatile("cp.async.commit_group;" ::: "memory");
}
__device__ __forceinline__ void mma_f16(float* d,
    uint32_t a0, uint32_t a1, uint32_t a2, uint32_t a3,
    uint32_t b0, uint32_t b1)
{
    asm volatile(
        "mma.sync.aligned.m16n8k16.row.col.f32.f16.f16.f32 "
        "{%0,%1,%2,%3}, {%4,%5,%6,%7}, {%8,%9}, {%0,%1,%2,%3};"
        : "+f"(d[0]), "+f"(d[1]), "+f"(d[2]), "+f"(d[3])
        : "r"(a0), "r"(a1), "r"(a2), "r"(a3), "r"(b0), "r"(b1));
}
__device__ __forceinline__ void ldsm4(uint32_t* r, uint32_t addr) {
    asm volatile("ldmatrix.sync.aligned.m8n8.x4.shared.b16 {%0,%1,%2,%3}, [%4];"
                 : "=r"(r[0]), "=r"(r[1]), "=r"(r[2]), "=r"(r[3]) : "r"(addr));
}
__device__ __forceinline__ void ldsm4t(uint32_t* r, uint32_t addr) {
    asm volatile("ldmatrix.sync.aligned.m8n8.x4.trans.shared.b16 {%0,%1,%2,%3}, [%4];"
                 : "=r"(r[0]), "=r"(r[1]), "=r"(r[2]), "=r"(r[3]) : "r"(addr));
}

#define QSCALE 0.18033688011112042f   // (1/8) * log2(e)

#define TLD2 36
#define STG32 (256 * TLD2)
#define FUSED_SMEM (3 * STG32 * 4)    // 110,592 B (gemm role; attn uses less)

// ---------------------------------------------------------------------------
// prep: x->fp16, both weight transposes, queue/counter reset (one launch)
// ---------------------------------------------------------------------------
__global__ void __launch_bounds__(256) prep_kernel(
    const float* __restrict__ x,
    const float* __restrict__ w_attn,
    const float* __restrict__ w_proj)
{
    const int bid = blockIdx.x;
    if (bid == 0 && threadIdx.x < 65) {
        if (threadIdx.x == 64) g_cursor = 0;
        else if (threadIdx.x < 32) g_qkv_done[threadIdx.x] = 0;
        else g_attn_done[threadIdx.x - 32] = 0;
    }
    if (bid < 4096) {
        int i = bid * 256 + threadIdx.x;
        float4 v = ((const float4*)x)[i];
        uint2 o;
        o.x = packh2(v.x, v.y);
        o.y = packh2(v.z, v.w);
        ((uint2*)g_x)[i] = o;
        return;
    }
    __shared__ float tile[32][33];
    const float* src;  __half* dst;  int R, C, c0, r0;
    if (bid < 7168) {
        int b2 = bid - 4096;
        src = w_attn;  dst = g_wT_attn;  R = NXD;  C = 3 * NXD;
        c0 = (b2 % 96) * 32;  r0 = (b2 / 96) * 32;
    } else {
        int b2 = bid - 7168;
        src = w_proj;  dst = g_wT_proj;  R = NXD;  C = NXD;
        c0 = (b2 % 32) * 32;  r0 = (b2 / 32) * 32;
    }
    int tx = threadIdx.x & 31, ty = threadIdx.x >> 5;
#pragma unroll
    for (int i = 0; i < 32; i += 8)
        tile[ty + i][tx] = src[(size_t)(r0 + ty + i) * C + c0 + tx];
    __syncthreads();
#pragma unroll
    for (int i = 0; i < 32; i += 8)
        dst[(size_t)(c0 + ty + i) * R + r0 + tx] = __float2half(tile[tx][ty + i]);
}

// ---------------------------------------------------------------------------
// GEMM role (from R14): block tile 128x128, BK=64, ldmatrix, 3-stage cp.async
// ---------------------------------------------------------------------------
__device__ void run_gemm(
    const __half* __restrict__ A, const __half* __restrict__ BT,
    const float* __restrict__ bias, float* __restrict__ Cout,
    float* __restrict__ present, int mode, int m0, int n0, uint32_t* sm32)
{
    const int t = threadIdx.x;
    const int lane = t & 31, w = t >> 5;
    const int wm = w >> 1, wn = w & 1;
    const int qr = lane >> 2, qc = lane & 3;

    uint32_t sa_[3], sb_[3];
#pragma unroll
    for (int s = 0; s < 3; s++) {
        sa_[s] = smem_u32(sm32 + s * STG32);
        sb_[s] = sa_[s] + 128 * TLD2 * 4;
    }

    const uint32_t a_loff = ((wm * 32 + (lane & 15)) * TLD2 + ((lane >> 4) << 2)) * 4;
    const uint32_t b_loff = ((wn * 64 + ((lane >> 4) << 3) + (lane & 7)) * TLD2
                             + (((lane >> 3) & 1) << 2)) * 4;

    float acc[2][8][4];
#pragma unroll
    for (int mt = 0; mt < 2; mt++)
#pragma unroll
        for (int nt = 0; nt < 8; nt++)
#pragma unroll
            for (int r = 0; r < 4; r++) acc[mt][nt][r] = 0.f;

#pragma unroll
    for (int s = 0; s < 2; s++) {
        const int k0 = s * 64;
#pragma unroll
        for (int i = 0; i < 4; i++) {
            int idx = t + i * 256;
            int row = idx >> 3, ch = idx & 7;
            cp16(sa_[s] + ((uint32_t)row * TLD2 + ch * 4) * 4,
                 A + (size_t)(m0 + row) * GK + k0 + ch * 8);
            cp16(sb_[s] + ((uint32_t)row * TLD2 + ch * 4) * 4,
                 BT + (size_t)(n0 + row) * GK + k0 + ch * 8);
        }
        cp_commit();
    }

    for (int kb = 0; kb < 16; kb++) {
        if (kb < 14)
            asm volatile("cp.async.wait_group 1;" ::: "memory");
        else
            asm volatile("cp.async.wait_group 0;" ::: "memory");
        __syncthreads();

        if (kb + 2 < 16) {
            const int s = (kb + 2) % 3;
            const int k0 = (kb + 2) * 64;
#pragma unroll
            for (int i = 0; i < 4; i++) {
                int idx = t + i * 256;
                int row = idx >> 3, ch = idx & 7;
                cp16(sa_[s] + ((uint32_t)row * TLD2 + ch * 4) * 4,
                     A + (size_t)(m0 + row) * GK + k0 + ch * 8);
                cp16(sb_[s] + ((uint32_t)row * TLD2 + ch * 4) * 4,
                     BT + (size_t)(n0 + row) * GK + k0 + ch * 8);
            }
            cp_commit();
        }

        const uint32_t a_addr = sa_[kb % 3] + a_loff;
        const uint32_t b_addr = sb_[kb % 3] + b_loff;
#pragma unroll
        for (int ks = 0; ks < 4; ks++) {
            uint32_t af[2][4], bf[4][4];
            ldsm4(af[0], a_addr + ks * 32);
            ldsm4(af[1], a_addr + 16 * TLD2 * 4 + ks * 32);
#pragma unroll
            for (int p = 0; p < 4; p++)
                ldsm4(bf[p], b_addr + p * 16 * TLD2 * 4 + ks * 32);
#pragma unroll
            for (int mt = 0; mt < 2; mt++)
#pragma unroll
                for (int nt = 0; nt < 8; nt++)
                    mma_f16(acc[mt][nt], af[mt][0], af[mt][1], af[mt][2], af[mt][3],
                            bf[nt >> 1][(nt & 1) * 2], bf[nt >> 1][(nt & 1) * 2 + 1]);
        }
    }

#pragma unroll
    for (int mt = 0; mt < 2; mt++) {
#pragma unroll
        for (int nt = 0; nt < 8; nt++) {
            int row = m0 + wm * 32 + mt * 16 + qr;
            int col = n0 + wn * 64 + nt * 8 + qc * 2;
            float bv0 = bias[col], bv1 = bias[col + 1];
            float v00 = acc[mt][nt][0] + bv0, v01 = acc[mt][nt][1] + bv1;
            float v10 = acc[mt][nt][2] + bv0, v11 = acc[mt][nt][3] + bv1;
            if (mode == 1) {
                *(float2*)(Cout + (size_t)row * NXD + col) = make_float2(v00, v01);
                *(float2*)(Cout + (size_t)(row + 8) * NXD + col) = make_float2(v10, v11);
            } else {
                int sec = col >> 10;
                int hn = col & 1023;
                int h = hn >> 6, d = hn & 63;
                int b0_ = row >> 10, s0_ = row & 1023;
                size_t i0 = (((size_t)b0_ * NHEAD + h) * SEQ + s0_) * HDIM + d;
                int b1_ = (row + 8) >> 10, s1_ = (row + 8) & 1023;
                size_t i1 = (((size_t)b1_ * NHEAD + h) * SEQ + s1_) * HDIM + d;
                if (sec == 0) {
                    *(uint32_t*)(g_q + i0) = packh2(v00 * QSCALE, v01 * QSCALE);
                    *(uint32_t*)(g_q + i1) = packh2(v10 * QSCALE, v11 * QSCALE);
                } else if (sec == 1) {
                    *(float2*)(present + i0) = make_float2(v00, v01);
                    *(float2*)(present + i1) = make_float2(v10, v11);
                    *(uint32_t*)(g_k + i0) = packh2(v00, v01);
                    *(uint32_t*)(g_k + i1) = packh2(v10, v11);
                } else {
                    float* pv = present + (size_t)BATCH * NHEAD * SEQ * HDIM;
                    *(float2*)(pv + i0) = make_float2(v00, v01);
                    *(float2*)(pv + i1) = make_float2(v10, v11);
                    *(uint32_t*)(g_v + i0) = packh2(v00, v01);
                    *(uint32_t*)(g_v + i1) = packh2(v10, v11);
                }
            }
        }
    }
}

// ---------------------------------------------------------------------------
// Attention role (from R14): fp16 mma, ldmatrix(.trans), exp2 softmax,
// diagonal-only masking, P register-resident.
// ---------------------------------------------------------------------------
__device__ void run_attn(int xr, int h, int b, uint32_t* sm32)
{
    uint32_t* Qs = sm32;                        // [128][36] h2
    uint32_t* Ksb = Qs + 128 * TLD2;            // 2 x [64][36]
    uint32_t* Vsb = Ksb + 2 * 64 * TLD2;        // 2 x [64][36]

    const int t = threadIdx.x;
    const int lane = t & 31, w = t >> 5;
    const int qr = lane >> 2, qc = lane & 3;
    const int q0 = xr * 128;

    const __half* qptr = g_q + ((size_t)b * NHEAD + h) * SEQ * HDIM;
    const __half* kptr = g_k + ((size_t)b * NHEAD + h) * SEQ * HDIM;
    const __half* vptr = g_v + ((size_t)b * NHEAD + h) * SEQ * HDIM;

    const uint32_t qs_a = smem_u32(Qs);
    const uint32_t ks_a[2] = { smem_u32(Ksb), smem_u32(Ksb + 64 * TLD2) };
    const uint32_t vs_a[2] = { smem_u32(Vsb), smem_u32(Vsb + 64 * TLD2) };

    const int wrow = w * 16;
    const uint32_t qa_loff = ((wrow + (lane & 15)) * TLD2 + ((lane >> 4) << 2)) * 4;
    const uint32_t kb_loff = ((((lane >> 4) << 3) + (lane & 7)) * TLD2
                              + (((lane >> 3) & 1) << 2)) * 4;
    const uint32_t vt_loff = (((((lane >> 3) & 1) << 3) + (lane & 7)) * TLD2
                              + ((lane >> 4) << 2)) * 4;

#pragma unroll
    for (int i = 0; i < 4; i++) {
        int c = t + i * 256;
        int row = c >> 3, ch = c & 7;
        cp16(qs_a + ((uint32_t)row * TLD2 + ch * 4) * 4,
             qptr + (size_t)(q0 + row) * HDIM + ch * 8);
    }
#pragma unroll
    for (int i = 0; i < 2; i++) {
        int c = t + i * 256;
        int row = c >> 3, ch = c & 7;
        uint32_t off = ((uint32_t)row * TLD2 + ch * 4) * 4;
        cp16(ks_a[0] + off, kptr + (size_t)row * HDIM + ch * 8);
        cp16(vs_a[0] + off, vptr + (size_t)row * HDIM + ch * 8);
    }
    cp_commit();

    float oacc[8][4];
#pragma unroll
    for (int nt = 0; nt < 8; nt++)
#pragma unroll
        for (int r = 0; r < 4; r++) oacc[nt][r] = 0.f;
    float m0 = -1e30f, m1 = -1e30f, l0 = 0.f, l1 = 0.f;

    const int qg0 = q0 + wrow + qr;
    const int qg1 = qg0 + 8;
    const int qmax = q0 + wrow + 15;
    const int nj = xr * 2 + 2;

    asm volatile("cp.async.wait_group 0;" ::: "memory");
    __syncthreads();
    uint32_t qf[4][4];
#pragma unroll
    for (int ks = 0; ks < 4; ks++)
        ldsm4(qf[ks], qs_a + qa_loff + ks * 32);

    for (int jt = 0; jt < nj; jt++) {
        const int j0 = jt * 64;
        if (jt > 0) {
            asm volatile("cp.async.wait_group 0;" ::: "memory");
            __syncthreads();
        }
        if (jt + 1 < nj) {
            const int buf = (jt + 1) & 1;
            const int jr = (jt + 1) * 64;
#pragma unroll
            for (int i = 0; i < 2; i++) {
                int c = t + i * 256;
                int row = c >> 3, ch = c & 7;
                uint32_t off = ((uint32_t)row * TLD2 + ch * 4) * 4;
                cp16(ks_a[buf] + off, kptr + (size_t)(jr + row) * HDIM + ch * 8);
                cp16(vs_a[buf] + off, vptr + (size_t)(jr + row) * HDIM + ch * 8);
            }
            cp_commit();
        }
        if (j0 > qmax) continue;

        const uint32_t k_addr = ks_a[jt & 1] + kb_loff;
        const uint32_t v_addr = vs_a[jt & 1] + vt_loff;

        float sacc[8][4];
#pragma unroll
        for (int nt = 0; nt < 8; nt++)
#pragma unroll
            for (int r = 0; r < 4; r++) sacc[nt][r] = 0.f;

#pragma unroll
        for (int ks = 0; ks < 4; ks++) {
            uint32_t kf[4][4];
#pragma unroll
            for (int p = 0; p < 4; p++)
                ldsm4(kf[p], k_addr + p * 16 * TLD2 * 4 + ks * 32);
#pragma unroll
            for (int nt = 0; nt < 8; nt++)
                mma_f16(sacc[nt], qf[ks][0], qf[ks][1], qf[ks][2], qf[ks][3],
                        kf[nt >> 1][(nt & 1) * 2], kf[nt >> 1][(nt & 1) * 2 + 1]);
        }

        float rx0 = -1e30f, rx1 = -1e30f;
        if (j0 + 63 > q0 + wrow) {
#pragma unroll
            for (int nt = 0; nt < 8; nt++) {
                int kg = j0 + nt * 8 + qc * 2;
                if (kg > qg0)     sacc[nt][0] = -1e30f;
                if (kg + 1 > qg0) sacc[nt][1] = -1e30f;
                if (kg > qg1)     sacc[nt][2] = -1e30f;
                if (kg + 1 > qg1) sacc[nt][3] = -1e30f;
            }
        }
#pragma unroll
        for (int nt = 0; nt < 8; nt++) {
            rx0 = fmaxf(rx0, fmaxf(sacc[nt][0], sacc[nt][1]));
            rx1 = fmaxf(rx1, fmaxf(sacc[nt][2], sacc[nt][3]));
        }
        rx0 = fmaxf(rx0, __shfl_xor_sync(0xffffffffu, rx0, 1));
        rx0 = fmaxf(rx0, __shfl_xor_sync(0xffffffffu, rx0, 2));
        rx1 = fmaxf(rx1, __shfl_xor_sync(0xffffffffu, rx1, 1));
        rx1 = fmaxf(rx1, __shfl_xor_sync(0xffffffffu, rx1, 2));

        float nm0 = fmaxf(m0, rx0), nm1 = fmaxf(m1, rx1);
        float cr0 = exp2f(m0 - nm0), cr1 = exp2f(m1 - nm1);

        float rs0 = 0.f, rs1 = 0.f;
        uint32_t plo[8], phi[8];
#pragma unroll
        for (int nt = 0; nt < 8; nt++) {
            float p00 = exp2f(sacc[nt][0] - nm0);
            float p01 = exp2f(sacc[nt][1] - nm0);
            float p10 = exp2f(sacc[nt][2] - nm1);
            float p11 = exp2f(sacc[nt][3] - nm1);
            rs0 += p00 + p01;
            rs1 += p10 + p11;
            plo[nt] = packh2(p00, p01);
            phi[nt] = packh2(p10, p11);
        }
        rs0 += __shfl_xor_sync(0xffffffffu, rs0, 1);
        rs0 += __shfl_xor_sync(0xffffffffu, rs0, 2);
        rs1 += __shfl_xor_sync(0xffffffffu, rs1, 1);
        rs1 += __shfl_xor_sync(0xffffffffu, rs1, 2);

        l0 = l0 * cr0 + rs0;  m0 = nm0;
        l1 = l1 * cr1 + rs1;  m1 = nm1;
#pragma unroll
        for (int nt = 0; nt < 8; nt++) {
            oacc[nt][0] *= cr0;  oacc[nt][1] *= cr0;
            oacc[nt][2] *= cr1;  oacc[nt][3] *= cr1;
        }

#pragma unroll
        for (int j = 0; j < 4; j++) {
            uint32_t vf[4][4];
#pragma unroll
            for (int p = 0; p < 4; p++)
                ldsm4t(vf[p], v_addr + j * 16 * TLD2 * 4 + p * 32);
            uint32_t a0 = plo[2 * j], a1 = phi[2 * j];
            uint32_t a2 = plo[2 * j + 1], a3 = phi[2 * j + 1];
#pragma unroll
            for (int nt = 0; nt < 8; nt++)
                mma_f16(oacc[nt], a0, a1, a2, a3,
                        vf[nt >> 1][(nt & 1) * 2], vf[nt >> 1][(nt & 1) * 2 + 1]);
        }
    }

    __syncthreads();
    float inv0 = 1.f / l0, inv1 = 1.f / l1;
#pragma unroll
    for (int nt = 0; nt < 8; nt++) {
        Qs[(wrow + qr) * TLD2 + nt * 4 + qc] =
            packh2(oacc[nt][0] * inv0, oacc[nt][1] * inv0);
        Qs[(wrow + qr + 8) * TLD2 + nt * 4 + qc] =
            packh2(oacc[nt][2] * inv1, oacc[nt][3] * inv1);
    }
    __syncthreads();
    for (int idx = t; idx < 128 * 32; idx += 256) {
        int row = idx >> 5, c2 = idx & 31;
        *(uint32_t*)(g_a + ((size_t)b * SEQ + q0 + row) * NXD + h * HDIM + c2 * 2) =
            Qs[row * TLD2 + c2];
    }
}

// ---------------------------------------------------------------------------
// Fused persistent kernel: 296 workers pull from the global queue.
// [0,768): qkv tiles; [768,1280): attn (long-first); [1280,1536): proj.
// ---------------------------------------------------------------------------
__global__ void __launch_bounds__(256, 2) fused_kernel(
    const float* __restrict__ b_attn, const float* __restrict__ b_proj,
    float* __restrict__ out, float* __restrict__ present)
{
    extern __shared__ uint32_t sm32[];
    __shared__ int s_item;

    for (;;) {
        if (threadIdx.x == 0) s_item = atomicAdd(&g_cursor, 1);
        __syncthreads();
        const int i = s_item;
        if (i >= N_ITEMS) return;

        if (i < N_QKV) {
            // qkv tile: m = i/24 (row-block), n = i%24
            const int m = i / 24, n = i % 24;
            run_gemm(g_x, g_wT_attn, b_attn, nullptr, present, 0,
                     m * 128, n * 128, sm32);
            __syncthreads();
            if (threadIdx.x == 0) {
                __threadfence();
                atomicAdd(&g_qkv_done[m], 1);    // m == b*8 + sblock
            }
        } else if (i < N_QKV + N_ATTN) {
            const int j = i - N_QKV;
            const int xr = 7 - (j >> 6);         // long tiles first
            const int h = (j & 63) >> 2;
            const int b = j & 3;
            if (threadIdx.x == 0) {
                for (int s = 0; s <= xr; s++)
                    while (*(volatile int*)&g_qkv_done[b * 8 + s] < 24)
                        __nanosleep(200);
            }
            __syncthreads();
            __threadfence();                     // acquire side of fence pair
            run_attn(xr, h, b, sm32);
            __syncthreads();
            if (threadIdx.x == 0) {
                __threadfence();
                atomicAdd(&g_attn_done[b * 8 + xr], 1);
            }
        } else {
            const int p = i - N_QKV - N_ATTN;
            const int m = p >> 3, n = p & 7;     // m == b*8 + sblock
            if (threadIdx.x == 0) {
                while (*(volatile int*)&g_attn_done[m] < 16)
                    __nanosleep(200);
            }
            __syncthreads();
            __threadfence();
            run_gemm(g_a, g_wT_proj, b_proj, out, nullptr, 1,
                     m * 128, n * 128, sm32);
        }
        __syncthreads();   // smem quiesced before next item
    }
}

// ---------------------------------------------------------------------------
extern "C" void kernel_launch(void* const* d_in, const int* in_sizes, int n_in,
                              void* d_out, int out_size)
{
    const float* x      = (const float*)d_in[0];
    const float* w_attn = (const float*)d_in[1];
    const float* b_attn = (const float*)d_in[2];
    const float* w_proj = (const float*)d_in[3];
    const float* b_proj = (const float*)d_in[4];

    float* out = (float*)d_out;
    float* present = out + (size_t)BATCH * SEQ * NXD;  // (2,B,NH,S,HD)

    cudaFuncSetAttribute(fused_kernel,
                         cudaFuncAttributeMaxDynamicSharedMemorySize, FUSED_SMEM);

    prep_kernel<<<8192, 256>>>(x, w_attn, w_proj);
    fused_kernel<<<296, 256, FUSED_SMEM>>>(b_attn, b_proj, out, present);
}